// round 3
// baseline (speedup 1.0000x reference)
#include <cuda_runtime.h>
#include <math.h>
#include <stdint.h>

#define Bb 64
#define Qn 64
#define Tt 448
#define Dd 512
#define FDd 1024
#define Hh 8
#define NL 2
#define FFf 2048
#define Ss 512
#define DH 64
#define BS (Bb*Ss)
#define BT (Bb*Tt)

// ---------------- scratch (device globals: allocation-free) ----------------
__device__ float g_x[(size_t)BS*Dd];
__device__ float g_tmp[(size_t)BS*Dd];
__device__ float g_q[(size_t)BS*Dd];
__device__ float g_k[(size_t)BS*Dd];
__device__ float g_v[(size_t)BS*Dd];
__device__ float g_h[(size_t)BS*FFf];
__device__ float g_sc[(size_t)Bb*Hh*Ss*Ss];

// ---------------- packed f32x2 helpers (sm_103a) ----------------
__device__ __forceinline__ void ffma2(unsigned long long& c, unsigned long long a, unsigned long long b) {
    asm("fma.rn.f32x2 %0, %1, %2, %0;" : "+l"(c) : "l"(a), "l"(b));
}
__device__ __forceinline__ unsigned long long dupf(float x) {
    unsigned long long r;
    asm("mov.b64 %0, {%1, %1};" : "=l"(r) : "f"(x));
    return r;
}
__device__ __forceinline__ float2 unpack2(unsigned long long v) {
    float2 r;
    asm("mov.b64 {%0, %1}, %2;" : "=f"(r.x), "=f"(r.y) : "l"(v));
    return r;
}

// ---------------- generic 128x128 SGEMM, C = A[M,K] @ W[K,N] + bias (+res / gelu) ----
enum { EPI_NONE = 0, EPI_RES = 1, EPI_GELU = 2 };

template<int EPI>
__global__ __launch_bounds__(256)
void gemm128(const float* __restrict__ A, const float* __restrict__ W,
             const float* __restrict__ bias, const float* __restrict__ res,
             float* __restrict__ C, int M, int N, int K)
{
    __shared__ float As[8][128];
    __shared__ float Bs[8][128];
    const int tid = threadIdx.x;
    const int bm = blockIdx.y * 128;
    const int bn = blockIdx.x * 128;
    const int tx = tid & 15, ty = tid >> 4;
    const int a_row = tid >> 1, a_col = (tid & 1) * 4;
    const int b_row = tid >> 5, b_col = (tid & 31) * 4;
    const float* Ap = A + (size_t)(bm + a_row) * K + a_col;
    const float* Wp = W + (size_t)b_row * N + (bn + b_col);

    unsigned long long acc2[4][8];   // pairs over row dim (i), 8 cols
    #pragma unroll
    for (int p = 0; p < 4; p++)
        #pragma unroll
        for (int j = 0; j < 8; j++) acc2[p][j] = 0ull;

    for (int k0 = 0; k0 < K; k0 += 8) {
        float4 av = *(const float4*)(Ap + k0);
        float4 wv = *(const float4*)(Wp + (size_t)k0 * N);
        As[a_col + 0][a_row] = av.x;
        As[a_col + 1][a_row] = av.y;
        As[a_col + 2][a_row] = av.z;
        As[a_col + 3][a_row] = av.w;
        *(float4*)&Bs[b_row][b_col] = wv;
        __syncthreads();
        #pragma unroll
        for (int kk = 0; kk < 8; kk++) {
            ulonglong2 a01 = *(const ulonglong2*)&As[kk][ty * 8];
            ulonglong2 a23 = *(const ulonglong2*)&As[kk][ty * 8 + 4];
            unsigned long long apair[4] = { a01.x, a01.y, a23.x, a23.y };
            float4 b0 = *(const float4*)&Bs[kk][tx * 8];
            float4 b1 = *(const float4*)&Bs[kk][tx * 8 + 4];
            float brr[8] = { b0.x, b0.y, b0.z, b0.w, b1.x, b1.y, b1.z, b1.w };
            unsigned long long bd[8];
            #pragma unroll
            for (int j = 0; j < 8; j++) bd[j] = dupf(brr[j]);
            #pragma unroll
            for (int p = 0; p < 4; p++)
                #pragma unroll
                for (int j = 0; j < 8; j++)
                    ffma2(acc2[p][j], apair[p], bd[j]);
        }
        __syncthreads();
    }

    #pragma unroll
    for (int p = 0; p < 4; p++) {
        int row0 = bm + ty * 8 + 2 * p;
        #pragma unroll
        for (int j = 0; j < 8; j++) {
            int col = bn + tx * 8 + j;
            float2 c = unpack2(acc2[p][j]);
            float v0 = c.x + bias[col];
            float v1 = c.y + bias[col];
            if (EPI == EPI_RES) {
                v0 += res[(size_t)row0 * N + col];
                v1 += res[(size_t)(row0 + 1) * N + col];
            }
            if (EPI == EPI_GELU) {
                v0 = 0.5f * v0 * (1.f + erff(v0 * 0.70710678118654752f));
                v1 = 0.5f * v1 * (1.f + erff(v1 * 0.70710678118654752f));
            }
            C[(size_t)row0 * N + col] = v0;
            C[(size_t)(row0 + 1) * N + col] = v1;
        }
    }
}

// ---------------- attention: scores = (Q K^T) * scale  (per b,h 64x64 tiles) -----
__global__ __launch_bounds__(256)
void attn_scores(const float* __restrict__ q, const float* __restrict__ k,
                 float* __restrict__ sc)
{
    __shared__ float Qs[64][65];
    __shared__ float Ks[64][65];
    const int bh = blockIdx.z;
    const int b = bh >> 3, h = bh & 7;
    const int s1_0 = blockIdx.y * 64, s2_0 = blockIdx.x * 64;
    const int tid = threadIdx.x;
    const int tx = tid & 15, ty = tid >> 4;

    for (int t = tid; t < 1024; t += 256) {
        int r = t >> 4, c = (t & 15) * 4;
        float4 qv = *(const float4*)(q + ((size_t)(b * Ss + s1_0 + r)) * Dd + h * DH + c);
        float4 kv = *(const float4*)(k + ((size_t)(b * Ss + s2_0 + r)) * Dd + h * DH + c);
        Qs[r][c] = qv.x; Qs[r][c + 1] = qv.y; Qs[r][c + 2] = qv.z; Qs[r][c + 3] = qv.w;
        Ks[r][c] = kv.x; Ks[r][c + 1] = kv.y; Ks[r][c + 2] = kv.z; Ks[r][c + 3] = kv.w;
    }
    __syncthreads();

    float acc[4][4];
    #pragma unroll
    for (int i = 0; i < 4; i++)
        #pragma unroll
        for (int j = 0; j < 4; j++) acc[i][j] = 0.f;

    #pragma unroll 8
    for (int kk = 0; kk < 64; kk++) {
        float ar[4], br[4];
        #pragma unroll
        for (int i = 0; i < 4; i++) ar[i] = Qs[ty * 4 + i][kk];
        #pragma unroll
        for (int j = 0; j < 4; j++) br[j] = Ks[tx * 4 + j][kk];
        #pragma unroll
        for (int i = 0; i < 4; i++)
            #pragma unroll
            for (int j = 0; j < 4; j++)
                acc[i][j] = fmaf(ar[i], br[j], acc[i][j]);
    }
    const float scale = 0.125f;  // 1/sqrt(64)
    #pragma unroll
    for (int i = 0; i < 4; i++)
        #pragma unroll
        for (int j = 0; j < 4; j++)
            sc[((size_t)bh * Ss + s1_0 + ty * 4 + i) * Ss + s2_0 + tx * 4 + j] = acc[i][j] * scale;
}

// ---------------- softmax with key-padding mask, row = (b,h,s1), S=512 --------
__global__ __launch_bounds__(256)
void softmax_mask(float* __restrict__ sc, const int* __restrict__ mask)
{
    __shared__ float red[8];
    const size_t row = blockIdx.x;
    const int b = (int)(blockIdx.x / (Hh * Ss));
    float* p = sc + row * Ss;
    const int* mr = mask + (size_t)b * Ss;
    const int tid = threadIdx.x;
    const float NEG = __int_as_float(0xff800000);

    float v0 = mr[tid] ? p[tid] : NEG;
    float v1 = mr[tid + 256] ? p[tid + 256] : NEG;

    float m = fmaxf(v0, v1);
    #pragma unroll
    for (int o = 16; o; o >>= 1) m = fmaxf(m, __shfl_xor_sync(0xffffffffu, m, o));
    if ((tid & 31) == 0) red[tid >> 5] = m;
    __syncthreads();
    m = red[0];
    #pragma unroll
    for (int i = 1; i < 8; i++) m = fmaxf(m, red[i]);
    __syncthreads();

    float e0 = expf(v0 - m), e1 = expf(v1 - m);
    float s = e0 + e1;
    #pragma unroll
    for (int o = 16; o; o >>= 1) s += __shfl_xor_sync(0xffffffffu, s, o);
    if ((tid & 31) == 0) red[tid >> 5] = s;
    __syncthreads();
    s = red[0] + red[1] + red[2] + red[3] + red[4] + red[5] + red[6] + red[7];

    float inv = 1.f / s;
    p[tid] = e0 * inv;
    p[tid + 256] = e1 * inv;
}

// ---------------- ctx = P @ V  (per b,h: [S,S]@[S,64]) -------------------------
__global__ __launch_bounds__(256)
void attn_ctx(const float* __restrict__ sc, const float* __restrict__ v,
              float* __restrict__ out)
{
    __shared__ float Ws[64][65];
    __shared__ float Vs[64][65];
    const int bh = blockIdx.z;
    const int b = bh >> 3, h = bh & 7;
    const int s1_0 = blockIdx.y * 64;
    const int tid = threadIdx.x;
    const int tx = tid & 15, ty = tid >> 4;

    float acc[4][4];
    #pragma unroll
    for (int i = 0; i < 4; i++)
        #pragma unroll
        for (int j = 0; j < 4; j++) acc[i][j] = 0.f;

    for (int k0 = 0; k0 < Ss; k0 += 64) {
        for (int t = tid; t < 1024; t += 256) {
            int r = t >> 4, c = (t & 15) * 4;
            float4 wv = *(const float4*)(sc + ((size_t)bh * Ss + s1_0 + r) * Ss + k0 + c);
            float4 vv = *(const float4*)(v + ((size_t)(b * Ss + k0 + r)) * Dd + h * DH + c);
            Ws[r][c] = wv.x; Ws[r][c + 1] = wv.y; Ws[r][c + 2] = wv.z; Ws[r][c + 3] = wv.w;
            Vs[r][c] = vv.x; Vs[r][c + 1] = vv.y; Vs[r][c + 2] = vv.z; Vs[r][c + 3] = vv.w;
        }
        __syncthreads();
        #pragma unroll 8
        for (int kk = 0; kk < 64; kk++) {
            float ar[4], br[4];
            #pragma unroll
            for (int i = 0; i < 4; i++) ar[i] = Ws[ty * 4 + i][kk];
            #pragma unroll
            for (int j = 0; j < 4; j++) br[j] = Vs[kk][tx * 4 + j];
            #pragma unroll
            for (int i = 0; i < 4; i++)
                #pragma unroll
                for (int j = 0; j < 4; j++)
                    acc[i][j] = fmaf(ar[i], br[j], acc[i][j]);
        }
        __syncthreads();
    }
    #pragma unroll
    for (int i = 0; i < 4; i++)
        #pragma unroll
        for (int j = 0; j < 4; j++)
            out[((size_t)(b * Ss + s1_0 + ty * 4 + i)) * Dd + h * DH + tx * 4 + j] = acc[i][j];
}

// ---------------- layernorm, one 128-thread block per 512-wide row -------------
__device__ __forceinline__ float block_sum_128(float v, float* red)
{
    #pragma unroll
    for (int o = 16; o; o >>= 1) v += __shfl_xor_sync(0xffffffffu, v, o);
    if ((threadIdx.x & 31) == 0) red[threadIdx.x >> 5] = v;
    __syncthreads();
    v = red[0] + red[1] + red[2] + red[3];
    __syncthreads();
    return v;
}

__global__ __launch_bounds__(128)
void ln_kernel(const float* __restrict__ in, float* __restrict__ out,
               const float* __restrict__ gamma, const float* __restrict__ beta,
               int vid_mode)
{
    __shared__ float red[4];
    const int r = blockIdx.x, tid = threadIdx.x;
    float4 v = *(const float4*)(in + (size_t)r * Dd + tid * 4);
    float s = block_sum_128(v.x + v.y + v.z + v.w, red);
    float mean = s * (1.f / Dd);
    float d0 = v.x - mean, d1 = v.y - mean, d2 = v.z - mean, d3 = v.w - mean;
    float sq = block_sum_128(d0 * d0 + d1 * d1 + d2 * d2 + d3 * d3, red);
    float inv = rsqrtf(sq * (1.f / Dd) + 1e-12f);
    int orow = vid_mode ? ((r / Tt) * Ss + Qn + (r % Tt)) : r;
    float4 gg = *(const float4*)(gamma + tid * 4);
    float4 bb = *(const float4*)(beta + tid * 4);
    float4 o;
    o.x = d0 * inv * gg.x + bb.x;
    o.y = d1 * inv * gg.y + bb.y;
    o.z = d2 * inv * gg.z + bb.z;
    o.w = d3 * inv * gg.w + bb.w;
    *(float4*)(out + (size_t)orow * Dd + tid * 4) = o;
}

// ------ concat question + add pos/mod embeddings + embedding layernorm ---------
__global__ __launch_bounds__(128)
void posmod_ln(const float* __restrict__ question, const float* __restrict__ pos,
               const float* __restrict__ mod, const float* __restrict__ gamma,
               const float* __restrict__ beta)
{
    __shared__ float red[4];
    const int r = blockIdx.x;       // b*S + s
    const int b = r / Ss, s = r % Ss;
    const int tid = threadIdx.x;
    float4 xv;
    if (s < Qn) xv = *(const float4*)(question + ((size_t)b * Qn + s) * Dd + tid * 4);
    else        xv = *(const float4*)(g_x + (size_t)r * Dd + tid * 4);
    float4 pv = *(const float4*)(pos + (size_t)s * Dd + tid * 4);
    const float* mrow = mod + (s < Qn ? 0 : Dd);
    float4 mv = *(const float4*)(mrow + tid * 4);
    xv.x += pv.x + mv.x; xv.y += pv.y + mv.y; xv.z += pv.z + mv.z; xv.w += pv.w + mv.w;

    float su = block_sum_128(xv.x + xv.y + xv.z + xv.w, red);
    float mean = su * (1.f / Dd);
    float d0 = xv.x - mean, d1 = xv.y - mean, d2 = xv.z - mean, d3 = xv.w - mean;
    float sq = block_sum_128(d0 * d0 + d1 * d1 + d2 * d2 + d3 * d3, red);
    float inv = rsqrtf(sq * (1.f / Dd) + 1e-12f);
    float4 gg = *(const float4*)(gamma + tid * 4);
    float4 bb = *(const float4*)(beta + tid * 4);
    float4 o;
    o.x = d0 * inv * gg.x + bb.x;
    o.y = d1 * inv * gg.y + bb.y;
    o.z = d2 * inv * gg.z + bb.z;
    o.w = d3 * inv * gg.w + bb.w;
    *(float4*)(g_x + (size_t)r * Dd + tid * 4) = o;
}

// -------------------------------- launch ---------------------------------------
extern "C" void kernel_launch(void* const* d_in, const int* in_sizes, int n_in,
                              void* d_out, int out_size)
{
    const float* video    = (const float*)d_in[0];
    const float* question = (const float*)d_in[1];
    const int*   mask     = (const int*)d_in[2];
    const float* pos_emb  = (const float*)d_in[3];
    const float* mod_emb  = (const float*)d_in[4];
    const float* Wv   = (const float*)d_in[5];
    const float* bv   = (const float*)d_in[6];
    const float* nv_g = (const float*)d_in[7];
    const float* nv_b = (const float*)d_in[8];
    const float* emb_g = (const float*)d_in[9];
    const float* emb_b = (const float*)d_in[10];
    const float* Wq  = (const float*)d_in[11];
    const float* bq  = (const float*)d_in[12];
    const float* Wk  = (const float*)d_in[13];
    const float* bk  = (const float*)d_in[14];
    const float* Wva = (const float*)d_in[15];
    const float* bva = (const float*)d_in[16];
    const float* Wo  = (const float*)d_in[17];
    const float* bo  = (const float*)d_in[18];
    const float* ln1g = (const float*)d_in[19];
    const float* ln1b = (const float*)d_in[20];
    const float* W1  = (const float*)d_in[21];
    const float* b1  = (const float*)d_in[22];
    const float* W2  = (const float*)d_in[23];
    const float* b2  = (const float*)d_in[24];
    const float* ln2g = (const float*)d_in[25];
    const float* ln2b = (const float*)d_in[26];
    float* out = (float*)d_out;

    float *x, *tmp, *q, *k, *v, *hbuf, *sc;
    cudaGetSymbolAddress((void**)&x,    g_x);
    cudaGetSymbolAddress((void**)&tmp,  g_tmp);
    cudaGetSymbolAddress((void**)&q,    g_q);
    cudaGetSymbolAddress((void**)&k,    g_k);
    cudaGetSymbolAddress((void**)&v,    g_v);
    cudaGetSymbolAddress((void**)&hbuf, g_h);
    cudaGetSymbolAddress((void**)&sc,   g_sc);

    // video projection + LN into x[:, Q:, :]
    gemm128<EPI_NONE><<<dim3(Dd / 128, BT / 128), 256>>>(video, Wv, bv, nullptr, tmp, BT, Dd, FDd);
    ln_kernel<<<BT, 128>>>(tmp, x, nv_g, nv_b, 1);
    // concat question + pos/mod + embedding LN (in place on x)
    posmod_ln<<<BS, 128>>>(question, pos_emb, mod_emb, emb_g, emb_b);

    for (int i = 0; i < NL; i++) {
        const size_t WO = (size_t)i * Dd * Dd;
        gemm128<EPI_NONE><<<dim3(Dd / 128, BS / 128), 256>>>(x, Wq + WO,  bq + i * Dd,  nullptr, q, BS, Dd, Dd);
        gemm128<EPI_NONE><<<dim3(Dd / 128, BS / 128), 256>>>(x, Wk + WO,  bk + i * Dd,  nullptr, k, BS, Dd, Dd);
        gemm128<EPI_NONE><<<dim3(Dd / 128, BS / 128), 256>>>(x, Wva + WO, bva + i * Dd, nullptr, v, BS, Dd, Dd);

        attn_scores<<<dim3(Ss / 64, Ss / 64, Bb * Hh), 256>>>(q, k, sc);
        softmax_mask<<<Bb * Hh * Ss, 256>>>(sc, mask);
        attn_ctx<<<dim3(1, Ss / 64, Bb * Hh), 256>>>(sc, v, q);   // ctx -> q (reuse)

        gemm128<EPI_RES><<<dim3(Dd / 128, BS / 128), 256>>>(q, Wo + WO, bo + i * Dd, x, tmp, BS, Dd, Dd);
        ln_kernel<<<BS, 128>>>(tmp, x, ln1g + i * Dd, ln1b + i * Dd, 0);

        gemm128<EPI_GELU><<<dim3(FFf / 128, BS / 128), 256>>>(x, W1 + (size_t)i * Dd * FFf, b1 + i * FFf,
                                                              nullptr, hbuf, BS, FFf, Dd);
        gemm128<EPI_RES><<<dim3(Dd / 128, BS / 128), 256>>>(hbuf, W2 + (size_t)i * FFf * Dd, b2 + i * Dd,
                                                            x, tmp, BS, Dd, FFf);
        float* dst = (i == NL - 1) ? out : x;
        ln_kernel<<<BS, 128>>>(tmp, dst, ln2g + i * Dd, ln2b + i * Dd, 0);
    }
}

// round 4
// speedup vs baseline: 1.0721x; 1.0721x over previous
#include <cuda_runtime.h>
#include <math.h>
#include <stdint.h>

#define Bb 64
#define Qn 64
#define Tt 448
#define Dd 512
#define FDd 1024
#define Hh 8
#define NL 2
#define FFf 2048
#define Ss 512
#define DH 64
#define BS (Bb*Ss)
#define BT (Bb*Tt)

// ---------------- scratch (device globals: allocation-free) ----------------
__device__ float g_x[(size_t)BS*Dd];
__device__ float g_tmp[(size_t)BS*Dd];
__device__ float g_q[(size_t)BS*Dd];
__device__ float g_k[(size_t)BS*Dd];
__device__ float g_v[(size_t)BS*Dd];
__device__ float g_h[(size_t)BS*FFf];
__device__ float g_sc[(size_t)Bb*Hh*Ss*Ss];

// ---------------- packed f32x2 helpers (sm_103a) ----------------
__device__ __forceinline__ void ffma2(unsigned long long& c, unsigned long long a, unsigned long long b) {
    asm("fma.rn.f32x2 %0, %1, %2, %0;" : "+l"(c) : "l"(a), "l"(b));
}
__device__ __forceinline__ unsigned long long dupf(float x) {
    unsigned long long r;
    asm("mov.b64 %0, {%1, %1};" : "=l"(r) : "f"(x));
    return r;
}
__device__ __forceinline__ float2 unpack2(unsigned long long v) {
    float2 r;
    asm("mov.b64 {%0, %1}, %2;" : "=f"(r.x), "=f"(r.y) : "l"(v));
    return r;
}

// ============ 128x128 SGEMM, BK=16, double-buffered, f32x2 ===================
enum { EPI_NONE = 0, EPI_RES = 1, EPI_GELU = 2 };

template<int EPI>
__global__ __launch_bounds__(256, 2)
void gemm128(const float* __restrict__ A, const float* __restrict__ W,
             const float* __restrict__ bias, const float* __restrict__ res,
             float* __restrict__ C, int M, int N, int K)
{
    __shared__ __align__(16) float As[2][16][132];   // padded rows (conflict-free STS)
    __shared__ __align__(16) float Bs[2][16][128];
    const int tid = threadIdx.x;
    const int bm = blockIdx.y * 128;
    const int bn = blockIdx.x * 128;
    const int tx = tid & 15, ty = tid >> 4;
    const int ar = tid >> 2, ac = (tid & 3) * 4;     // A: 64 rows x 16 cols per pass, 2 passes
    const int br = tid >> 4, bc = (tid & 15) * 8;    // B: 16 rows x 128 cols
    const float* Aptr  = A + (size_t)(bm + ar) * K + ac;
    const float* A2ptr = Aptr + (size_t)64 * K;
    const float* Bptr  = W + (size_t)br * N + bn + bc;

    unsigned long long acc2[4][8];
    #pragma unroll
    for (int p = 0; p < 4; p++)
        #pragma unroll
        for (int j = 0; j < 8; j++) acc2[p][j] = 0ull;

    float4 a0, a1, b0, b1;
    // prologue: tile 0
    a0 = *(const float4*)(Aptr);
    a1 = *(const float4*)(A2ptr);
    b0 = *(const float4*)(Bptr);
    b1 = *(const float4*)(Bptr + 4);
    As[0][ac + 0][ar] = a0.x; As[0][ac + 1][ar] = a0.y; As[0][ac + 2][ar] = a0.z; As[0][ac + 3][ar] = a0.w;
    As[0][ac + 0][ar + 64] = a1.x; As[0][ac + 1][ar + 64] = a1.y; As[0][ac + 2][ar + 64] = a1.z; As[0][ac + 3][ar + 64] = a1.w;
    *(float4*)&Bs[0][br][bc] = b0;
    *(float4*)&Bs[0][br][bc + 4] = b1;
    __syncthreads();

    const int TT = K >> 4;
    for (int t = 0; t < TT; t++) {
        const int cur = t & 1;
        if (t + 1 < TT) {                           // prefetch next tile into regs
            const int k0 = (t + 1) << 4;
            a0 = *(const float4*)(Aptr + k0);
            a1 = *(const float4*)(A2ptr + k0);
            b0 = *(const float4*)(Bptr + (size_t)k0 * N);
            b1 = *(const float4*)(Bptr + (size_t)k0 * N + 4);
        }
        #pragma unroll
        for (int kk = 0; kk < 16; kk++) {
            ulonglong2 a01 = *(const ulonglong2*)&As[cur][kk][ty * 8];
            ulonglong2 a23 = *(const ulonglong2*)&As[cur][kk][ty * 8 + 4];
            unsigned long long ap[4] = { a01.x, a01.y, a23.x, a23.y };
            float4 q0 = *(const float4*)&Bs[cur][kk][tx * 8];
            float4 q1 = *(const float4*)&Bs[cur][kk][tx * 8 + 4];
            unsigned long long bd[8] = { dupf(q0.x), dupf(q0.y), dupf(q0.z), dupf(q0.w),
                                         dupf(q1.x), dupf(q1.y), dupf(q1.z), dupf(q1.w) };
            #pragma unroll
            for (int p = 0; p < 4; p++)
                #pragma unroll
                for (int j = 0; j < 8; j++)
                    ffma2(acc2[p][j], ap[p], bd[j]);
        }
        __syncthreads();
        if (t + 1 < TT) {
            const int nb = cur ^ 1;
            As[nb][ac + 0][ar] = a0.x; As[nb][ac + 1][ar] = a0.y; As[nb][ac + 2][ar] = a0.z; As[nb][ac + 3][ar] = a0.w;
            As[nb][ac + 0][ar + 64] = a1.x; As[nb][ac + 1][ar + 64] = a1.y; As[nb][ac + 2][ar + 64] = a1.z; As[nb][ac + 3][ar + 64] = a1.w;
            *(float4*)&Bs[nb][br][bc] = b0;
            *(float4*)&Bs[nb][br][bc + 4] = b1;
            __syncthreads();
        }
    }

    #pragma unroll
    for (int p = 0; p < 4; p++) {
        int row0 = bm + ty * 8 + 2 * p;
        #pragma unroll
        for (int j = 0; j < 8; j++) {
            int col = bn + tx * 8 + j;
            float2 c = unpack2(acc2[p][j]);
            float v0 = c.x + bias[col];
            float v1 = c.y + bias[col];
            if (EPI == EPI_RES) {
                v0 += res[(size_t)row0 * N + col];
                v1 += res[(size_t)(row0 + 1) * N + col];
            }
            if (EPI == EPI_GELU) {
                v0 = 0.5f * v0 * (1.f + erff(v0 * 0.70710678118654752f));
                v1 = 0.5f * v1 * (1.f + erff(v1 * 0.70710678118654752f));
            }
            C[(size_t)row0 * N + col] = v0;
            C[(size_t)(row0 + 1) * N + col] = v1;
        }
    }
}

// ============ scores = (Q K^T)*scale — 128x128 tiles, f32x2 ==================
__global__ __launch_bounds__(256, 2)
void attn_scores(const float* __restrict__ q, const float* __restrict__ k,
                 float* __restrict__ sc)
{
    __shared__ __align__(16) float Qs[32][132];
    __shared__ __align__(16) float Ks[32][132];
    const int bh = blockIdx.z;
    const int b = bh >> 3, h = bh & 7;
    const int s1_0 = blockIdx.y * 128, s2_0 = blockIdx.x * 128;
    const int tid = threadIdx.x;
    const int tx = tid & 15, ty = tid >> 4;

    unsigned long long acc2[4][8];
    #pragma unroll
    for (int p = 0; p < 4; p++)
        #pragma unroll
        for (int j = 0; j < 8; j++) acc2[p][j] = 0ull;

    #pragma unroll
    for (int kt = 0; kt < 2; kt++) {
        for (int t = tid; t < 1024; t += 256) {          // 128 rows x 8 float4
            int r = t >> 3, c = (t & 7) * 4;
            float4 qv = *(const float4*)(q + ((size_t)(b * Ss + s1_0 + r)) * Dd + h * DH + kt * 32 + c);
            float4 kv = *(const float4*)(k + ((size_t)(b * Ss + s2_0 + r)) * Dd + h * DH + kt * 32 + c);
            Qs[c + 0][r] = qv.x; Qs[c + 1][r] = qv.y; Qs[c + 2][r] = qv.z; Qs[c + 3][r] = qv.w;
            Ks[c + 0][r] = kv.x; Ks[c + 1][r] = kv.y; Ks[c + 2][r] = kv.z; Ks[c + 3][r] = kv.w;
        }
        __syncthreads();
        #pragma unroll
        for (int kk = 0; kk < 32; kk++) {
            ulonglong2 a01 = *(const ulonglong2*)&Qs[kk][ty * 8];
            ulonglong2 a23 = *(const ulonglong2*)&Qs[kk][ty * 8 + 4];
            unsigned long long ap[4] = { a01.x, a01.y, a23.x, a23.y };
            float4 q0 = *(const float4*)&Ks[kk][tx * 8];
            float4 q1 = *(const float4*)&Ks[kk][tx * 8 + 4];
            unsigned long long bd[8] = { dupf(q0.x), dupf(q0.y), dupf(q0.z), dupf(q0.w),
                                         dupf(q1.x), dupf(q1.y), dupf(q1.z), dupf(q1.w) };
            #pragma unroll
            for (int p = 0; p < 4; p++)
                #pragma unroll
                for (int j = 0; j < 8; j++)
                    ffma2(acc2[p][j], ap[p], bd[j]);
        }
        __syncthreads();
    }

    const float scale = 0.125f;   // 1/sqrt(64)
    #pragma unroll
    for (int p = 0; p < 4; p++) {
        int row0 = s1_0 + ty * 8 + 2 * p;
        #pragma unroll
        for (int j = 0; j < 8; j++) {
            int col = s2_0 + tx * 8 + j;
            float2 c = unpack2(acc2[p][j]);
            sc[((size_t)bh * Ss + row0) * Ss + col] = c.x * scale;
            sc[((size_t)bh * Ss + row0 + 1) * Ss + col] = c.y * scale;
        }
    }
}

// ============ softmax with key-padding mask, row = (b,h,s1) ==================
__global__ __launch_bounds__(256)
void softmax_mask(float* __restrict__ sc, const int* __restrict__ mask)
{
    __shared__ float red[8];
    const size_t row = blockIdx.x;
    const int b = (int)(blockIdx.x / (Hh * Ss));
    float* p = sc + row * Ss;
    const int* mr = mask + (size_t)b * Ss;
    const int tid = threadIdx.x;
    const float NEG = __int_as_float(0xff800000);

    float v0 = mr[tid] ? p[tid] : NEG;
    float v1 = mr[tid + 256] ? p[tid + 256] : NEG;

    float m = fmaxf(v0, v1);
    #pragma unroll
    for (int o = 16; o; o >>= 1) m = fmaxf(m, __shfl_xor_sync(0xffffffffu, m, o));
    if ((tid & 31) == 0) red[tid >> 5] = m;
    __syncthreads();
    m = red[0];
    #pragma unroll
    for (int i = 1; i < 8; i++) m = fmaxf(m, red[i]);
    __syncthreads();

    float e0 = __expf(v0 - m), e1 = __expf(v1 - m);
    float s = e0 + e1;
    #pragma unroll
    for (int o = 16; o; o >>= 1) s += __shfl_xor_sync(0xffffffffu, s, o);
    if ((tid & 31) == 0) red[tid >> 5] = s;
    __syncthreads();
    s = red[0] + red[1] + red[2] + red[3] + red[4] + red[5] + red[6] + red[7];

    float inv = 1.f / s;
    p[tid] = e0 * inv;
    p[tid + 256] = e1 * inv;
}

// ============ ctx = P @ V — 128x64 tiles, f32x2 ==============================
__global__ __launch_bounds__(128, 4)
void attn_ctx(const float* __restrict__ sc, const float* __restrict__ v,
              float* __restrict__ out)
{
    __shared__ __align__(16) float Ws[32][132];
    __shared__ __align__(16) float Vs[32][64];
    const int bh = blockIdx.z;
    const int b = bh >> 3, h = bh & 7;
    const int s1_0 = blockIdx.y * 128;
    const int tid = threadIdx.x;
    const int tx = tid & 7, ty = tid >> 3;   // 8 cols x 16 row-groups

    unsigned long long acc2[4][8];
    #pragma unroll
    for (int p = 0; p < 4; p++)
        #pragma unroll
        for (int j = 0; j < 8; j++) acc2[p][j] = 0ull;

    for (int k0 = 0; k0 < Ss; k0 += 32) {
        for (int t = tid; t < 1024; t += 128) {          // Ws: 128 rows x 8 float4
            int r = t >> 3, c = (t & 7) * 4;
            float4 wv = *(const float4*)(sc + ((size_t)bh * Ss + s1_0 + r) * Ss + k0 + c);
            Ws[c + 0][r] = wv.x; Ws[c + 1][r] = wv.y; Ws[c + 2][r] = wv.z; Ws[c + 3][r] = wv.w;
        }
        for (int t = tid; t < 512; t += 128) {           // Vs: 32 rows x 16 float4
            int r = t >> 4, c = (t & 15) * 4;
            float4 vv = *(const float4*)(v + ((size_t)(b * Ss + k0 + r)) * Dd + h * DH + c);
            *(float4*)&Vs[r][c] = vv;
        }
        __syncthreads();
        #pragma unroll
        for (int kk = 0; kk < 32; kk++) {
            ulonglong2 a01 = *(const ulonglong2*)&Ws[kk][ty * 8];
            ulonglong2 a23 = *(const ulonglong2*)&Ws[kk][ty * 8 + 4];
            unsigned long long ap[4] = { a01.x, a01.y, a23.x, a23.y };
            float4 q0 = *(const float4*)&Vs[kk][tx * 8];
            float4 q1 = *(const float4*)&Vs[kk][tx * 8 + 4];
            unsigned long long bd[8] = { dupf(q0.x), dupf(q0.y), dupf(q0.z), dupf(q0.w),
                                         dupf(q1.x), dupf(q1.y), dupf(q1.z), dupf(q1.w) };
            #pragma unroll
            for (int p = 0; p < 4; p++)
                #pragma unroll
                for (int j = 0; j < 8; j++)
                    ffma2(acc2[p][j], ap[p], bd[j]);
        }
        __syncthreads();
    }

    #pragma unroll
    for (int p = 0; p < 4; p++) {
        int row0 = s1_0 + ty * 8 + 2 * p;
        #pragma unroll
        for (int j = 0; j < 8; j++) {
            int col = h * DH + tx * 8 + j;
            float2 c = unpack2(acc2[p][j]);
            out[((size_t)(b * Ss + row0)) * Dd + col] = c.x;
            out[((size_t)(b * Ss + row0 + 1)) * Dd + col] = c.y;
        }
    }
}

// ============ layernorm helpers ==============================================
__device__ __forceinline__ float block_sum_128(float v, float* red)
{
    #pragma unroll
    for (int o = 16; o; o >>= 1) v += __shfl_xor_sync(0xffffffffu, v, o);
    if ((threadIdx.x & 31) == 0) red[threadIdx.x >> 5] = v;
    __syncthreads();
    v = red[0] + red[1] + red[2] + red[3];
    __syncthreads();
    return v;
}

__global__ __launch_bounds__(128)
void ln_kernel(const float* __restrict__ in, float* __restrict__ out,
               const float* __restrict__ gamma, const float* __restrict__ beta,
               int vid_mode)
{
    __shared__ float red[4];
    const int r = blockIdx.x, tid = threadIdx.x;
    float4 v = *(const float4*)(in + (size_t)r * Dd + tid * 4);
    float s = block_sum_128(v.x + v.y + v.z + v.w, red);
    float mean = s * (1.f / Dd);
    float d0 = v.x - mean, d1 = v.y - mean, d2 = v.z - mean, d3 = v.w - mean;
    float sq = block_sum_128(d0 * d0 + d1 * d1 + d2 * d2 + d3 * d3, red);
    float inv = rsqrtf(sq * (1.f / Dd) + 1e-12f);
    int orow = vid_mode ? ((r / Tt) * Ss + Qn + (r % Tt)) : r;
    float4 gg = *(const float4*)(gamma + tid * 4);
    float4 bb = *(const float4*)(beta + tid * 4);
    float4 o;
    o.x = d0 * inv * gg.x + bb.x;
    o.y = d1 * inv * gg.y + bb.y;
    o.z = d2 * inv * gg.z + bb.z;
    o.w = d3 * inv * gg.w + bb.w;
    *(float4*)(out + (size_t)orow * Dd + tid * 4) = o;
}

__global__ __launch_bounds__(128)
void posmod_ln(const float* __restrict__ question, const float* __restrict__ pos,
               const float* __restrict__ mod, const float* __restrict__ gamma,
               const float* __restrict__ beta)
{
    __shared__ float red[4];
    const int r = blockIdx.x;       // b*S + s
    const int b = r / Ss, s = r % Ss;
    const int tid = threadIdx.x;
    float4 xv;
    if (s < Qn) xv = *(const float4*)(question + ((size_t)b * Qn + s) * Dd + tid * 4);
    else        xv = *(const float4*)(g_x + (size_t)r * Dd + tid * 4);
    float4 pv = *(const float4*)(pos + (size_t)s * Dd + tid * 4);
    const float* mrow = mod + (s < Qn ? 0 : Dd);
    float4 mv = *(const float4*)(mrow + tid * 4);
    xv.x += pv.x + mv.x; xv.y += pv.y + mv.y; xv.z += pv.z + mv.z; xv.w += pv.w + mv.w;

    float su = block_sum_128(xv.x + xv.y + xv.z + xv.w, red);
    float mean = su * (1.f / Dd);
    float d0 = xv.x - mean, d1 = xv.y - mean, d2 = xv.z - mean, d3 = xv.w - mean;
    float sq = block_sum_128(d0 * d0 + d1 * d1 + d2 * d2 + d3 * d3, red);
    float inv = rsqrtf(sq * (1.f / Dd) + 1e-12f);
    float4 gg = *(const float4*)(gamma + tid * 4);
    float4 bb = *(const float4*)(beta + tid * 4);
    float4 o;
    o.x = d0 * inv * gg.x + bb.x;
    o.y = d1 * inv * gg.y + bb.y;
    o.z = d2 * inv * gg.z + bb.z;
    o.w = d3 * inv * gg.w + bb.w;
    *(float4*)(g_x + (size_t)r * Dd + tid * 4) = o;
}

// -------------------------------- launch ---------------------------------------
extern "C" void kernel_launch(void* const* d_in, const int* in_sizes, int n_in,
                              void* d_out, int out_size)
{
    const float* video    = (const float*)d_in[0];
    const float* question = (const float*)d_in[1];
    const int*   mask     = (const int*)d_in[2];
    const float* pos_emb  = (const float*)d_in[3];
    const float* mod_emb  = (const float*)d_in[4];
    const float* Wv   = (const float*)d_in[5];
    const float* bv   = (const float*)d_in[6];
    const float* nv_g = (const float*)d_in[7];
    const float* nv_b = (const float*)d_in[8];
    const float* emb_g = (const float*)d_in[9];
    const float* emb_b = (const float*)d_in[10];
    const float* Wq  = (const float*)d_in[11];
    const float* bq  = (const float*)d_in[12];
    const float* Wk  = (const float*)d_in[13];
    const float* bk  = (const float*)d_in[14];
    const float* Wva = (const float*)d_in[15];
    const float* bva = (const float*)d_in[16];
    const float* Wo  = (const float*)d_in[17];
    const float* bo  = (const float*)d_in[18];
    const float* ln1g = (const float*)d_in[19];
    const float* ln1b = (const float*)d_in[20];
    const float* W1  = (const float*)d_in[21];
    const float* b1  = (const float*)d_in[22];
    const float* W2  = (const float*)d_in[23];
    const float* b2  = (const float*)d_in[24];
    const float* ln2g = (const float*)d_in[25];
    const float* ln2b = (const float*)d_in[26];
    float* out = (float*)d_out;

    float *x, *tmp, *q, *k, *v, *hbuf, *sc;
    cudaGetSymbolAddress((void**)&x,    g_x);
    cudaGetSymbolAddress((void**)&tmp,  g_tmp);
    cudaGetSymbolAddress((void**)&q,    g_q);
    cudaGetSymbolAddress((void**)&k,    g_k);
    cudaGetSymbolAddress((void**)&v,    g_v);
    cudaGetSymbolAddress((void**)&hbuf, g_h);
    cudaGetSymbolAddress((void**)&sc,   g_sc);

    // video projection + LN into x[:, Q:, :]
    gemm128<EPI_NONE><<<dim3(Dd / 128, BT / 128), 256>>>(video, Wv, bv, nullptr, tmp, BT, Dd, FDd);
    ln_kernel<<<BT, 128>>>(tmp, x, nv_g, nv_b, 1);
    // concat question + pos/mod + embedding LN (in place on x)
    posmod_ln<<<BS, 128>>>(question, pos_emb, mod_emb, emb_g, emb_b);

    for (int i = 0; i < NL; i++) {
        const size_t WO = (size_t)i * Dd * Dd;
        gemm128<EPI_NONE><<<dim3(Dd / 128, BS / 128), 256>>>(x, Wq + WO,  bq + i * Dd,  nullptr, q, BS, Dd, Dd);
        gemm128<EPI_NONE><<<dim3(Dd / 128, BS / 128), 256>>>(x, Wk + WO,  bk + i * Dd,  nullptr, k, BS, Dd, Dd);
        gemm128<EPI_NONE><<<dim3(Dd / 128, BS / 128), 256>>>(x, Wva + WO, bva + i * Dd, nullptr, v, BS, Dd, Dd);

        attn_scores<<<dim3(Ss / 128, Ss / 128, Bb * Hh), 256>>>(q, k, sc);
        softmax_mask<<<Bb * Hh * Ss, 256>>>(sc, mask);
        attn_ctx<<<dim3(1, Ss / 128, Bb * Hh), 128>>>(sc, v, q);   // ctx -> q (reuse)

        gemm128<EPI_RES><<<dim3(Dd / 128, BS / 128), 256>>>(q, Wo + WO, bo + i * Dd, x, tmp, BS, Dd, Dd);
        ln_kernel<<<BS, 128>>>(tmp, x, ln1g + i * Dd, ln1b + i * Dd, 0);

        gemm128<EPI_GELU><<<dim3(FFf / 128, BS / 128), 256>>>(x, W1 + (size_t)i * Dd * FFf, b1 + i * FFf,
                                                              nullptr, hbuf, BS, FFf, Dd);
        gemm128<EPI_RES><<<dim3(Dd / 128, BS / 128), 256>>>(hbuf, W2 + (size_t)i * FFf * Dd, b2 + i * Dd,
                                                            x, tmp, BS, Dd, FFf);
        float* dst = (i == NL - 1) ? out : x;
        ln_kernel<<<BS, 128>>>(tmp, dst, ln2g + i * Dd, ln2b + i * Dd, 0);
    }
}

// round 7
// speedup vs baseline: 1.5084x; 1.4069x over previous
#include <cuda_runtime.h>
#include <cuda_bf16.h>
#include <math.h>
#include <stdint.h>

#define Bb 64
#define Qn 64
#define Tt 448
#define Dd 512
#define FDd 1024
#define Hh 8
#define NL 2
#define FFf 2048
#define Ss 512
#define DH 64
#define BS (Bb*Ss)
#define BT (Bb*Tt)

// ---------------- scratch (device globals: allocation-free) ----------------
__device__ float g_x[(size_t)BS*Dd];
__device__ float g_tmp[(size_t)BS*Dd];
__device__ float g_q[(size_t)BS*Dd];
__device__ float g_k[(size_t)BS*Dd];
__device__ float g_v[(size_t)BS*Dd];
__device__ float g_h[(size_t)BS*FFf];
__device__ float g_sc[(size_t)Bb*Hh*Ss*Ss];
// split-bf16 operand buffers
__device__ __nv_bfloat16 ga_hi[(size_t)BS*FFf];
__device__ __nv_bfloat16 ga_lo[(size_t)BS*FFf];
__device__ __nv_bfloat16 gw_hi[(size_t)FFf*Dd];
__device__ __nv_bfloat16 gw_lo[(size_t)FFf*Dd];

// ---------------- f32x2 helpers (attention kernels) ----------------
__device__ __forceinline__ void ffma2(unsigned long long& c, unsigned long long a, unsigned long long b) {
    asm("fma.rn.f32x2 %0, %1, %2, %0;" : "+l"(c) : "l"(a), "l"(b));
}
__device__ __forceinline__ unsigned long long dupf(float x) {
    unsigned long long r;
    asm("mov.b64 %0, {%1, %1};" : "=l"(r) : "f"(x));
    return r;
}
__device__ __forceinline__ float2 unpack2(unsigned long long v) {
    float2 r;
    asm("mov.b64 {%0, %1}, %2;" : "=f"(r.x), "=f"(r.y) : "l"(v));
    return r;
}

// ---------------- mma.sync helpers ----------------
__device__ __forceinline__ uint32_t smem_u32(const void* p) {
    uint32_t a;
    asm("{ .reg .u64 t; cvta.to.shared.u64 t, %1; cvt.u32.u64 %0, t; }" : "=r"(a) : "l"(p));
    return a;
}
__device__ __forceinline__ void ldm4(uint32_t* r, uint32_t addr) {
    asm volatile("ldmatrix.sync.aligned.m8n8.x4.shared.b16 {%0,%1,%2,%3}, [%4];"
                 : "=r"(r[0]), "=r"(r[1]), "=r"(r[2]), "=r"(r[3]) : "r"(addr));
}
__device__ __forceinline__ void mma16816(float* c, const uint32_t* a, uint32_t b0, uint32_t b1) {
    asm volatile("mma.sync.aligned.m16n8k16.row.col.f32.bf16.bf16.f32 "
                 "{%0,%1,%2,%3}, {%4,%5,%6,%7}, {%8,%9}, {%0,%1,%2,%3};"
                 : "+f"(c[0]), "+f"(c[1]), "+f"(c[2]), "+f"(c[3])
                 : "r"(a[0]), "r"(a[1]), "r"(a[2]), "r"(a[3]), "r"(b0), "r"(b1));
}
__device__ __forceinline__ void cpasync16(uint32_t dst, const void* src) {
    asm volatile("cp.async.cg.shared.global [%0], [%1], 16;" :: "r"(dst), "l"(src));
}

// smem geometry: 4 operand tiles (A_hi, A_lo, B_hi, B_lo), each 128 rows x 80B pitch
#define OPB   10240
#define STAGE 40960
#define SMEM_MMA (2 * STAGE)

// ============ split conversion kernels ============
__global__ __launch_bounds__(256)
void split_kernel(const float* __restrict__ in, __nv_bfloat16* __restrict__ hi,
                  __nv_bfloat16* __restrict__ lo, size_t n4)
{
    size_t i = (size_t)blockIdx.x * 256 + threadIdx.x;
    if (i >= n4) return;
    float4 v = ((const float4*)in)[i];
    __nv_bfloat16 h0 = __float2bfloat16(v.x), h1 = __float2bfloat16(v.y);
    __nv_bfloat16 h2 = __float2bfloat16(v.z), h3 = __float2bfloat16(v.w);
    __nv_bfloat16 l0 = __float2bfloat16(v.x - __bfloat162float(h0));
    __nv_bfloat16 l1 = __float2bfloat16(v.y - __bfloat162float(h1));
    __nv_bfloat16 l2 = __float2bfloat16(v.z - __bfloat162float(h2));
    __nv_bfloat16 l3 = __float2bfloat16(v.w - __bfloat162float(h3));
    ((__nv_bfloat162*)hi)[2 * i] = __nv_bfloat162(h0, h1);
    ((__nv_bfloat162*)hi)[2 * i + 1] = __nv_bfloat162(h2, h3);
    ((__nv_bfloat162*)lo)[2 * i] = __nv_bfloat162(l0, l1);
    ((__nv_bfloat162*)lo)[2 * i + 1] = __nv_bfloat162(l2, l3);
}

// W[K][N] fp32 -> out[N][K] split bf16
__global__ __launch_bounds__(256)
void transpose_split(const float* __restrict__ W, __nv_bfloat16* __restrict__ hi,
                     __nv_bfloat16* __restrict__ lo, int K, int N)
{
    __shared__ float t[32][33];
    const int n0 = blockIdx.x * 32, k0 = blockIdx.y * 32;
    const int tx = threadIdx.x, ty = threadIdx.y;
    #pragma unroll
    for (int j = 0; j < 4; j++)
        t[ty + j * 8][tx] = W[(size_t)(k0 + ty + j * 8) * N + n0 + tx];
    __syncthreads();
    #pragma unroll
    for (int j = 0; j < 4; j++) {
        int n = n0 + ty + j * 8, kk = k0 + tx;
        float v = t[tx][ty + j * 8];
        __nv_bfloat16 h = __float2bfloat16(v);
        __nv_bfloat16 l = __float2bfloat16(v - __bfloat162float(h));
        hi[(size_t)n * K + kk] = h;
        lo[(size_t)n * K + kk] = l;
    }
}

// ============ HMMA split-bf16 GEMM: C = A@W^T(+bias)(+res/gelu) ==============
enum { EPI_NONE = 0, EPI_RES = 1, EPI_GELU = 2 };

template<int EPI>
__global__ __launch_bounds__(256, 1)
void gemm_mma(const __nv_bfloat16* __restrict__ a_hi, const __nv_bfloat16* __restrict__ a_lo,
              const __nv_bfloat16* __restrict__ w_hi, const __nv_bfloat16* __restrict__ w_lo,
              const float* __restrict__ bias, const float* __restrict__ res,
              float* __restrict__ C, int M, int N, int K)
{
    extern __shared__ __align__(16) char smem[];
    const uint32_t sb = smem_u32(smem);
    const int tid = threadIdx.x;
    const int lane = tid & 31, wid = tid >> 5;
    const int wm = wid & 3, wn = wid >> 2;          // 4 x 2 warp grid
    const int bm = blockIdx.y * 128, bn = blockIdx.x * 128;

    // ---- cp.async geometry: thread -> (row, 2 chunks of 16B) ----
    const int crow = tid & 127;
    const int cch = (tid >> 7) * 2;                 // 0 or 2
    const char* gsrc[4];
    gsrc[0] = (const char*)a_hi + (size_t)(bm + crow) * K * 2;
    gsrc[1] = (const char*)a_lo + (size_t)(bm + crow) * K * 2;
    gsrc[2] = (const char*)w_hi + (size_t)(bn + crow) * K * 2;
    gsrc[3] = (const char*)w_lo + (size_t)(bn + crow) * K * 2;
    uint32_t sdst[4];
    #pragma unroll
    for (int op = 0; op < 4; op++)
        sdst[op] = sb + op * OPB + crow * 80 + cch * 16;

    // ---- ldmatrix per-thread base addresses (stage 0) ----
    const uint32_t a_off = (uint32_t)((wm * 32 + (lane & 15)) * 80 + ((lane >> 4) & 1) * 16);
    const uint32_t b_off = (uint32_t)((wn * 64 + ((lane >> 4) << 3) + (lane & 7)) * 80 + ((lane >> 3) & 1) * 16);
    const uint32_t aH = sb + a_off;                 // A_hi
    const uint32_t aL = sb + OPB + a_off;           // A_lo
    const uint32_t bH = sb + 2 * OPB + b_off;       // B_hi
    const uint32_t bL = sb + 3 * OPB + b_off;       // B_lo

    float acc[2][8][4];
    #pragma unroll
    for (int mf = 0; mf < 2; mf++)
        #pragma unroll
        for (int nf = 0; nf < 8; nf++)
            #pragma unroll
            for (int e = 0; e < 4; e++) acc[mf][nf][e] = 0.f;

    const int NC = K >> 5;

    // prologue: stage 0 (k-chunk 0)
    #pragma unroll
    for (int op = 0; op < 4; op++) {
        cpasync16(sdst[op], gsrc[op] + (cch + 0) * 16);
        cpasync16(sdst[op] + 16, gsrc[op] + (cch + 1) * 16);
    }
    asm volatile("cp.async.commit_group;" ::: "memory");

    for (int c = 0; c < NC; c++) {
        if (c + 1 < NC) {
            const uint32_t so = (uint32_t)(((c + 1) & 1) * STAGE);
            const size_t go = (size_t)(c + 1) * 64;
            #pragma unroll
            for (int op = 0; op < 4; op++) {
                cpasync16(sdst[op] + so, gsrc[op] + go + (cch + 0) * 16);
                cpasync16(sdst[op] + so + 16, gsrc[op] + go + (cch + 1) * 16);
            }
            asm volatile("cp.async.commit_group;" ::: "memory");
            asm volatile("cp.async.wait_group 1;" ::: "memory");
        } else {
            asm volatile("cp.async.wait_group 0;" ::: "memory");
        }
        __syncthreads();

        const uint32_t so = (uint32_t)((c & 1) * STAGE);
        #pragma unroll
        for (int ks = 0; ks < 2; ks++) {
            uint32_t ah[2][4], al[2][4];
            #pragma unroll
            for (int mf = 0; mf < 2; mf++) {
                ldm4(ah[mf], aH + so + mf * (16 * 80) + ks * 32);
                ldm4(al[mf], aL + so + mf * (16 * 80) + ks * 32);
            }
            #pragma unroll
            for (int p = 0; p < 4; p++) {
                uint32_t bh[4], bl[4];
                ldm4(bh, bH + so + p * (16 * 80) + ks * 32);
                ldm4(bl, bL + so + p * (16 * 80) + ks * 32);
                #pragma unroll
                for (int mf = 0; mf < 2; mf++) {
                    mma16816(acc[mf][2 * p],     ah[mf], bh[0], bh[1]);
                    mma16816(acc[mf][2 * p + 1], ah[mf], bh[2], bh[3]);
                    mma16816(acc[mf][2 * p],     al[mf], bh[0], bh[1]);
                    mma16816(acc[mf][2 * p + 1], al[mf], bh[2], bh[3]);
                    mma16816(acc[mf][2 * p],     ah[mf], bl[0], bl[1]);
                    mma16816(acc[mf][2 * p + 1], ah[mf], bl[2], bl[3]);
                }
            }
        }
        __syncthreads();
    }

    // ---- epilogue ----
    const int r0 = bm + wm * 32 + (lane >> 2);
    const int cb = bn + wn * 64 + (lane & 3) * 2;
    #pragma unroll
    for (int mf = 0; mf < 2; mf++) {
        #pragma unroll
        for (int nf = 0; nf < 8; nf++) {
            const int row = r0 + mf * 16;
            const int col = cb + nf * 8;
            float2 bv = *(const float2*)(bias + col);
            float v0 = acc[mf][nf][0] + bv.x, v1 = acc[mf][nf][1] + bv.y;
            float v2 = acc[mf][nf][2] + bv.x, v3 = acc[mf][nf][3] + bv.y;
            if (EPI == EPI_RES) {
                float2 ra = *(const float2*)(res + (size_t)row * N + col);
                float2 rb = *(const float2*)(res + (size_t)(row + 8) * N + col);
                v0 += ra.x; v1 += ra.y; v2 += rb.x; v3 += rb.y;
            }
            if (EPI == EPI_GELU) {
                v0 = 0.5f * v0 * (1.f + erff(v0 * 0.70710678118654752f));
                v1 = 0.5f * v1 * (1.f + erff(v1 * 0.70710678118654752f));
                v2 = 0.5f * v2 * (1.f + erff(v2 * 0.70710678118654752f));
                v3 = 0.5f * v3 * (1.f + erff(v3 * 0.70710678118654752f));
            }
            *(float2*)(C + (size_t)row * N + col) = make_float2(v0, v1);
            *(float2*)(C + (size_t)(row + 8) * N + col) = make_float2(v2, v3);
        }
    }
}

// ============ scores = (Q K^T)*scale — 128x128 tiles, f32x2 ==================
__global__ __launch_bounds__(256, 2)
void attn_scores(const float* __restrict__ q, const float* __restrict__ k,
                 float* __restrict__ sc)
{
    __shared__ __align__(16) float Qs[32][132];
    __shared__ __align__(16) float Ks[32][132];
    const int bh = blockIdx.z;
    const int b = bh >> 3, h = bh & 7;
    const int s1_0 = blockIdx.y * 128, s2_0 = blockIdx.x * 128;
    const int tid = threadIdx.x;
    const int tx = tid & 15, ty = tid >> 4;

    unsigned long long acc2[4][8];
    #pragma unroll
    for (int p = 0; p < 4; p++)
        #pragma unroll
        for (int j = 0; j < 8; j++) acc2[p][j] = 0ull;

    #pragma unroll
    for (int kt = 0; kt < 2; kt++) {
        for (int t = tid; t < 1024; t += 256) {
            int r = t >> 3, c = (t & 7) * 4;
            float4 qv = *(const float4*)(q + ((size_t)(b * Ss + s1_0 + r)) * Dd + h * DH + kt * 32 + c);
            float4 kv = *(const float4*)(k + ((size_t)(b * Ss + s2_0 + r)) * Dd + h * DH + kt * 32 + c);
            Qs[c + 0][r] = qv.x; Qs[c + 1][r] = qv.y; Qs[c + 2][r] = qv.z; Qs[c + 3][r] = qv.w;
            Ks[c + 0][r] = kv.x; Ks[c + 1][r] = kv.y; Ks[c + 2][r] = kv.z; Ks[c + 3][r] = kv.w;
        }
        __syncthreads();
        #pragma unroll
        for (int kk = 0; kk < 32; kk++) {
            ulonglong2 a01 = *(const ulonglong2*)&Qs[kk][ty * 8];
            ulonglong2 a23 = *(const ulonglong2*)&Qs[kk][ty * 8 + 4];
            unsigned long long ap[4] = { a01.x, a01.y, a23.x, a23.y };
            float4 q0 = *(const float4*)&Ks[kk][tx * 8];
            float4 q1 = *(const float4*)&Ks[kk][tx * 8 + 4];
            unsigned long long bd[8] = { dupf(q0.x), dupf(q0.y), dupf(q0.z), dupf(q0.w),
                                         dupf(q1.x), dupf(q1.y), dupf(q1.z), dupf(q1.w) };
            #pragma unroll
            for (int p = 0; p < 4; p++)
                #pragma unroll
                for (int j = 0; j < 8; j++)
                    ffma2(acc2[p][j], ap[p], bd[j]);
        }
        __syncthreads();
    }

    const float scale = 0.125f;
    #pragma unroll
    for (int p = 0; p < 4; p++) {
        int row0 = s1_0 + ty * 8 + 2 * p;
        #pragma unroll
        for (int j = 0; j < 8; j++) {
            int col = s2_0 + tx * 8 + j;
            float2 c = unpack2(acc2[p][j]);
            sc[((size_t)bh * Ss + row0) * Ss + col] = c.x * scale;
            sc[((size_t)bh * Ss + row0 + 1) * Ss + col] = c.y * scale;
        }
    }
}

// ============ softmax with key-padding mask ==================================
__global__ __launch_bounds__(256)
void softmax_mask(float* __restrict__ sc, const int* __restrict__ mask)
{
    __shared__ float red[8];
    const size_t row = blockIdx.x;
    const int b = (int)(blockIdx.x / (Hh * Ss));
    float* p = sc + row * Ss;
    const int* mr = mask + (size_t)b * Ss;
    const int tid = threadIdx.x;
    const float NEG = __int_as_float(0xff800000);

    float v0 = mr[tid] ? p[tid] : NEG;
    float v1 = mr[tid + 256] ? p[tid + 256] : NEG;

    float m = fmaxf(v0, v1);
    #pragma unroll
    for (int o = 16; o; o >>= 1) m = fmaxf(m, __shfl_xor_sync(0xffffffffu, m, o));
    if ((tid & 31) == 0) red[tid >> 5] = m;
    __syncthreads();
    m = red[0];
    #pragma unroll
    for (int i = 1; i < 8; i++) m = fmaxf(m, red[i]);
    __syncthreads();

    float e0 = __expf(v0 - m), e1 = __expf(v1 - m);
    float s = e0 + e1;
    #pragma unroll
    for (int o = 16; o; o >>= 1) s += __shfl_xor_sync(0xffffffffu, s, o);
    if ((tid & 31) == 0) red[tid >> 5] = s;
    __syncthreads();
    s = red[0] + red[1] + red[2] + red[3] + red[4] + red[5] + red[6] + red[7];

    float inv = 1.f / s;
    p[tid] = e0 * inv;
    p[tid + 256] = e1 * inv;
}

// ============ ctx = P @ V — 128x64 tiles, f32x2 ==============================
__global__ __launch_bounds__(128, 4)
void attn_ctx(const float* __restrict__ sc, const float* __restrict__ v,
              float* __restrict__ out)
{
    __shared__ __align__(16) float Ws[32][132];
    __shared__ __align__(16) float Vs[32][64];
    const int bh = blockIdx.z;
    const int b = bh >> 3, h = bh & 7;
    const int s1_0 = blockIdx.y * 128;
    const int tid = threadIdx.x;
    const int tx = tid & 7, ty = tid >> 3;

    unsigned long long acc2[4][8];
    #pragma unroll
    for (int p = 0; p < 4; p++)
        #pragma unroll
        for (int j = 0; j < 8; j++) acc2[p][j] = 0ull;

    for (int k0 = 0; k0 < Ss; k0 += 32) {
        for (int t = tid; t < 1024; t += 128) {
            int r = t >> 3, c = (t & 7) * 4;
            float4 wv = *(const float4*)(sc + ((size_t)bh * Ss + s1_0 + r) * Ss + k0 + c);
            Ws[c + 0][r] = wv.x; Ws[c + 1][r] = wv.y; Ws[c + 2][r] = wv.z; Ws[c + 3][r] = wv.w;
        }
        for (int t = tid; t < 512; t += 128) {
            int r = t >> 4, c = (t & 15) * 4;
            float4 vv = *(const float4*)(v + ((size_t)(b * Ss + k0 + r)) * Dd + h * DH + c);
            *(float4*)&Vs[r][c] = vv;
        }
        __syncthreads();
        #pragma unroll
        for (int kk = 0; kk < 32; kk++) {
            ulonglong2 a01 = *(const ulonglong2*)&Ws[kk][ty * 8];
            ulonglong2 a23 = *(const ulonglong2*)&Ws[kk][ty * 8 + 4];
            unsigned long long ap[4] = { a01.x, a01.y, a23.x, a23.y };
            float4 q0 = *(const float4*)&Vs[kk][tx * 8];
            float4 q1 = *(const float4*)&Vs[kk][tx * 8 + 4];
            unsigned long long bd[8] = { dupf(q0.x), dupf(q0.y), dupf(q0.z), dupf(q0.w),
                                         dupf(q1.x), dupf(q1.y), dupf(q1.z), dupf(q1.w) };
            #pragma unroll
            for (int p = 0; p < 4; p++)
                #pragma unroll
                for (int j = 0; j < 8; j++)
                    ffma2(acc2[p][j], ap[p], bd[j]);
        }
        __syncthreads();
    }

    #pragma unroll
    for (int p = 0; p < 4; p++) {
        int row0 = s1_0 + ty * 8 + 2 * p;
        #pragma unroll
        for (int j = 0; j < 8; j++) {
            int col = h * DH + tx * 8 + j;
            float2 c = unpack2(acc2[p][j]);
            out[((size_t)(b * Ss + row0)) * Dd + col] = c.x;
            out[((size_t)(b * Ss + row0 + 1)) * Dd + col] = c.y;
        }
    }
}

// ============ layernorm helpers ==============================================
__device__ __forceinline__ float block_sum_128(float v, float* red)
{
    #pragma unroll
    for (int o = 16; o; o >>= 1) v += __shfl_xor_sync(0xffffffffu, v, o);
    if ((threadIdx.x & 31) == 0) red[threadIdx.x >> 5] = v;
    __syncthreads();
    v = red[0] + red[1] + red[2] + red[3];
    __syncthreads();
    return v;
}

__global__ __launch_bounds__(128)
void ln_kernel(const float* __restrict__ in, float* __restrict__ out,
               const float* __restrict__ gamma, const float* __restrict__ beta,
               int vid_mode)
{
    __shared__ float red[4];
    const int r = blockIdx.x, tid = threadIdx.x;
    float4 v = *(const float4*)(in + (size_t)r * Dd + tid * 4);
    float s = block_sum_128(v.x + v.y + v.z + v.w, red);
    float mean = s * (1.f / Dd);
    float d0 = v.x - mean, d1 = v.y - mean, d2 = v.z - mean, d3 = v.w - mean;
    float sq = block_sum_128(d0 * d0 + d1 * d1 + d2 * d2 + d3 * d3, red);
    float inv = rsqrtf(sq * (1.f / Dd) + 1e-12f);
    int orow = vid_mode ? ((r / Tt) * Ss + Qn + (r % Tt)) : r;
    float4 gg = *(const float4*)(gamma + tid * 4);
    float4 bb = *(const float4*)(beta + tid * 4);
    float4 o;
    o.x = d0 * inv * gg.x + bb.x;
    o.y = d1 * inv * gg.y + bb.y;
    o.z = d2 * inv * gg.z + bb.z;
    o.w = d3 * inv * gg.w + bb.w;
    *(float4*)(out + (size_t)orow * Dd + tid * 4) = o;
}

__global__ __launch_bounds__(128)
void posmod_ln(const float* __restrict__ question, const float* __restrict__ pos,
               const float* __restrict__ mod, const float* __restrict__ gamma,
               const float* __restrict__ beta)
{
    __shared__ float red[4];
    const int r = blockIdx.x;
    const int b = r / Ss, s = r % Ss;
    const int tid = threadIdx.x;
    float4 xv;
    if (s < Qn) xv = *(const float4*)(question + ((size_t)b * Qn + s) * Dd + tid * 4);
    else        xv = *(const float4*)(g_x + (size_t)r * Dd + tid * 4);
    float4 pv = *(const float4*)(pos + (size_t)s * Dd + tid * 4);
    const float* mrow = mod + (s < Qn ? 0 : Dd);
    float4 mv = *(const float4*)(mrow + tid * 4);
    xv.x += pv.x + mv.x; xv.y += pv.y + mv.y; xv.z += pv.z + mv.z; xv.w += pv.w + mv.w;

    float su = block_sum_128(xv.x + xv.y + xv.z + xv.w, red);
    float mean = su * (1.f / Dd);
    float d0 = xv.x - mean, d1 = xv.y - mean, d2 = xv.z - mean, d3 = xv.w - mean;
    float sq = block_sum_128(d0 * d0 + d1 * d1 + d2 * d2 + d3 * d3, red);
    float inv = rsqrtf(sq * (1.f / Dd) + 1e-12f);
    float4 gg = *(const float4*)(gamma + tid * 4);
    float4 bb = *(const float4*)(beta + tid * 4);
    float4 o;
    o.x = d0 * inv * gg.x + bb.x;
    o.y = d1 * inv * gg.y + bb.y;
    o.z = d2 * inv * gg.z + bb.z;
    o.w = d3 * inv * gg.w + bb.w;
    *(float4*)(g_x + (size_t)r * Dd + tid * 4) = o;
}

// -------------------------------- launch ---------------------------------------
extern "C" void kernel_launch(void* const* d_in, const int* in_sizes, int n_in,
                              void* d_out, int out_size)
{
    const float* video    = (const float*)d_in[0];
    const float* question = (const float*)d_in[1];
    const int*   mask     = (const int*)d_in[2];
    const float* pos_emb  = (const float*)d_in[3];
    const float* mod_emb  = (const float*)d_in[4];
    const float* Wv   = (const float*)d_in[5];
    const float* bv   = (const float*)d_in[6];
    const float* nv_g = (const float*)d_in[7];
    const float* nv_b = (const float*)d_in[8];
    const float* emb_g = (const float*)d_in[9];
    const float* emb_b = (const float*)d_in[10];
    const float* Wq  = (const float*)d_in[11];
    const float* bq  = (const float*)d_in[12];
    const float* Wk  = (const float*)d_in[13];
    const float* bk  = (const float*)d_in[14];
    const float* Wva = (const float*)d_in[15];
    const float* bva = (const float*)d_in[16];
    const float* Wo  = (const float*)d_in[17];
    const float* bo  = (const float*)d_in[18];
    const float* ln1g = (const float*)d_in[19];
    const float* ln1b = (const float*)d_in[20];
    const float* W1  = (const float*)d_in[21];
    const float* b1  = (const float*)d_in[22];
    const float* W2  = (const float*)d_in[23];
    const float* b2  = (const float*)d_in[24];
    const float* ln2g = (const float*)d_in[25];
    const float* ln2b = (const float*)d_in[26];
    float* out = (float*)d_out;

    float *x, *tmp, *q, *k, *v, *hbuf, *sc;
    __nv_bfloat16 *ah, *al, *wh, *wl;
    cudaGetSymbolAddress((void**)&x,    g_x);
    cudaGetSymbolAddress((void**)&tmp,  g_tmp);
    cudaGetSymbolAddress((void**)&q,    g_q);
    cudaGetSymbolAddress((void**)&k,    g_k);
    cudaGetSymbolAddress((void**)&v,    g_v);
    cudaGetSymbolAddress((void**)&hbuf, g_h);
    cudaGetSymbolAddress((void**)&sc,   g_sc);
    cudaGetSymbolAddress((void**)&ah,   ga_hi);
    cudaGetSymbolAddress((void**)&al,   ga_lo);
    cudaGetSymbolAddress((void**)&wh,   gw_hi);
    cudaGetSymbolAddress((void**)&wl,   gw_lo);

    cudaFuncSetAttribute(gemm_mma<EPI_NONE>, cudaFuncAttributeMaxDynamicSharedMemorySize, SMEM_MMA);
    cudaFuncSetAttribute(gemm_mma<EPI_RES>,  cudaFuncAttributeMaxDynamicSharedMemorySize, SMEM_MMA);
    cudaFuncSetAttribute(gemm_mma<EPI_GELU>, cudaFuncAttributeMaxDynamicSharedMemorySize, SMEM_MMA);

    auto split = [&](const float* src, size_t n) {
        size_t n4 = n / 4;
        split_kernel<<<(unsigned)((n4 + 255) / 256), 256>>>(src, ah, al, n4);
    };
    auto tsplit = [&](const float* W, int K, int N) {
        transpose_split<<<dim3(N / 32, K / 32), dim3(32, 8)>>>(W, wh, wl, K, N);
    };

    // video projection + LN into x[:, Q:, :]
    split(video, (size_t)BT * FDd);
    tsplit(Wv, FDd, Dd);
    gemm_mma<EPI_NONE><<<dim3(Dd / 128, BT / 128), 256, SMEM_MMA>>>(ah, al, wh, wl, bv, nullptr, tmp, BT, Dd, FDd);
    ln_kernel<<<BT, 128>>>(tmp, x, nv_g, nv_b, 1);
    posmod_ln<<<BS, 128>>>(question, pos_emb, mod_emb, emb_g, emb_b);

    for (int i = 0; i < NL; i++) {
        const size_t WO = (size_t)i * Dd * Dd;
        split(x, (size_t)BS * Dd);
        tsplit(Wq + WO, Dd, Dd);
        gemm_mma<EPI_NONE><<<dim3(Dd / 128, BS / 128), 256, SMEM_MMA>>>(ah, al, wh, wl, bq + i * Dd, nullptr, q, BS, Dd, Dd);
        tsplit(Wk + WO, Dd, Dd);
        gemm_mma<EPI_NONE><<<dim3(Dd / 128, BS / 128), 256, SMEM_MMA>>>(ah, al, wh, wl, bk + i * Dd, nullptr, k, BS, Dd, Dd);
        tsplit(Wva + WO, Dd, Dd);
        gemm_mma<EPI_NONE><<<dim3(Dd / 128, BS / 128), 256, SMEM_MMA>>>(ah, al, wh, wl, bva + i * Dd, nullptr, v, BS, Dd, Dd);

        attn_scores<<<dim3(Ss / 128, Ss / 128, Bb * Hh), 256>>>(q, k, sc);
        softmax_mask<<<Bb * Hh * Ss, 256>>>(sc, mask);
        attn_ctx<<<dim3(1, Ss / 128, Bb * Hh), 128>>>(sc, v, q);   // ctx -> q

        split(q, (size_t)BS * Dd);
        tsplit(Wo + WO, Dd, Dd);
        gemm_mma<EPI_RES><<<dim3(Dd / 128, BS / 128), 256, SMEM_MMA>>>(ah, al, wh, wl, bo + i * Dd, x, tmp, BS, Dd, Dd);
        ln_kernel<<<BS, 128>>>(tmp, x, ln1g + i * Dd, ln1b + i * Dd, 0);

        split(x, (size_t)BS * Dd);
        tsplit(W1 + (size_t)i * Dd * FFf, Dd, FFf);
        gemm_mma<EPI_GELU><<<dim3(FFf / 128, BS / 128), 256, SMEM_MMA>>>(ah, al, wh, wl, b1 + i * FFf, nullptr, hbuf, BS, FFf, Dd);

        split(hbuf, (size_t)BS * FFf);
        tsplit(W2 + (size_t)i * FFf * Dd, FFf, Dd);
        gemm_mma<EPI_RES><<<dim3(Dd / 128, BS / 128), 256, SMEM_MMA>>>(ah, al, wh, wl, b2 + i * Dd, x, tmp, BS, Dd, FFf);

        float* dst = (i == NL - 1) ? out : x;
        ln_kernel<<<BS, 128>>>(tmp, dst, ln2g + i * Dd, ln2b + i * Dd, 0);
    }
}

// round 8
// speedup vs baseline: 1.6932x; 1.1226x over previous
#include <cuda_runtime.h>
#include <cuda_bf16.h>
#include <math.h>
#include <stdint.h>

#define Bb 64
#define Qn 64
#define Tt 448
#define Dd 512
#define FDd 1024
#define Hh 8
#define NL 2
#define FFf 2048
#define Ss 512
#define DH 64
#define BS (Bb*Ss)
#define BT (Bb*Tt)

// ---------------- scratch (device globals: allocation-free) ----------------
__device__ float g_x[(size_t)BS*Dd];
__device__ float g_tmp[(size_t)BS*Dd];
__device__ float g_q[(size_t)BS*Dd];
__device__ float g_k[(size_t)BS*Dd];
__device__ float g_v[(size_t)BS*Dd];
__device__ float g_sc[(size_t)Bb*Hh*Ss*Ss];
// split-bf16 operand buffers: ga (large: hbuf/video), gb (x/ctx), gw (weights)
__device__ __nv_bfloat16 ga_hi[(size_t)BS*FFf];
__device__ __nv_bfloat16 ga_lo[(size_t)BS*FFf];
__device__ __nv_bfloat16 gb_hi[(size_t)BS*Dd];
__device__ __nv_bfloat16 gb_lo[(size_t)BS*Dd];
__device__ __nv_bfloat16 gw_hi[(size_t)FFf*Dd];
__device__ __nv_bfloat16 gw_lo[(size_t)FFf*Dd];

// ---------------- f32x2 helpers (attention kernels) ----------------
__device__ __forceinline__ void ffma2(unsigned long long& c, unsigned long long a, unsigned long long b) {
    asm("fma.rn.f32x2 %0, %1, %2, %0;" : "+l"(c) : "l"(a), "l"(b));
}
__device__ __forceinline__ unsigned long long dupf(float x) {
    unsigned long long r;
    asm("mov.b64 %0, {%1, %1};" : "=l"(r) : "f"(x));
    return r;
}
__device__ __forceinline__ float2 unpack2(unsigned long long v) {
    float2 r;
    asm("mov.b64 {%0, %1}, %2;" : "=f"(r.x), "=f"(r.y) : "l"(v));
    return r;
}
__device__ __forceinline__ void split1(float v, __nv_bfloat16& h, __nv_bfloat16& l) {
    h = __float2bfloat16(v);
    l = __float2bfloat16(v - __bfloat162float(h));
}

// ---------------- mma.sync helpers ----------------
__device__ __forceinline__ uint32_t smem_u32(const void* p) {
    uint32_t a;
    asm("{ .reg .u64 t; cvta.to.shared.u64 t, %1; cvt.u32.u64 %0, t; }" : "=r"(a) : "l"(p));
    return a;
}
__device__ __forceinline__ void ldm4(uint32_t* r, uint32_t addr) {
    asm volatile("ldmatrix.sync.aligned.m8n8.x4.shared.b16 {%0,%1,%2,%3}, [%4];"
                 : "=r"(r[0]), "=r"(r[1]), "=r"(r[2]), "=r"(r[3]) : "r"(addr));
}
__device__ __forceinline__ void mma16816(float* c, const uint32_t* a, uint32_t b0, uint32_t b1) {
    asm volatile("mma.sync.aligned.m16n8k16.row.col.f32.bf16.bf16.f32 "
                 "{%0,%1,%2,%3}, {%4,%5,%6,%7}, {%8,%9}, {%0,%1,%2,%3};"
                 : "+f"(c[0]), "+f"(c[1]), "+f"(c[2]), "+f"(c[3])
                 : "r"(a[0]), "r"(a[1]), "r"(a[2]), "r"(a[3]), "r"(b0), "r"(b1));
}
__device__ __forceinline__ void cpasync16(uint32_t dst, const void* src) {
    asm volatile("cp.async.cg.shared.global [%0], [%1], 16;" :: "r"(dst), "l"(src));
}

// smem geometry: 4 operand tiles (A_hi, A_lo, B_hi, B_lo), each 128 rows x 80B pitch
#define OPB   10240
#define STAGE 40960
#define SMEM_MMA (2 * STAGE)

// ============ split conversion (video input only) ============
__global__ __launch_bounds__(256)
void split_kernel(const float* __restrict__ in, __nv_bfloat16* __restrict__ hi,
                  __nv_bfloat16* __restrict__ lo, size_t n4)
{
    size_t i = (size_t)blockIdx.x * 256 + threadIdx.x;
    if (i >= n4) return;
    float4 v = ((const float4*)in)[i];
    __nv_bfloat16 h0, h1, h2, h3, l0, l1, l2, l3;
    split1(v.x, h0, l0); split1(v.y, h1, l1); split1(v.z, h2, l2); split1(v.w, h3, l3);
    ((__nv_bfloat162*)hi)[2 * i] = __nv_bfloat162(h0, h1);
    ((__nv_bfloat162*)hi)[2 * i + 1] = __nv_bfloat162(h2, h3);
    ((__nv_bfloat162*)lo)[2 * i] = __nv_bfloat162(l0, l1);
    ((__nv_bfloat162*)lo)[2 * i + 1] = __nv_bfloat162(l2, l3);
}

// W[K][N] fp32 -> out[N][K] split bf16
__global__ __launch_bounds__(256)
void transpose_split(const float* __restrict__ W, __nv_bfloat16* __restrict__ hi,
                     __nv_bfloat16* __restrict__ lo, int K, int N)
{
    __shared__ float t[32][33];
    const int n0 = blockIdx.x * 32, k0 = blockIdx.y * 32;
    const int tx = threadIdx.x, ty = threadIdx.y;
    #pragma unroll
    for (int j = 0; j < 4; j++)
        t[ty + j * 8][tx] = W[(size_t)(k0 + ty + j * 8) * N + n0 + tx];
    __syncthreads();
    #pragma unroll
    for (int j = 0; j < 4; j++) {
        int n = n0 + ty + j * 8, kk = k0 + tx;
        __nv_bfloat16 h, l;
        split1(t[tx][ty + j * 8], h, l);
        hi[(size_t)n * K + kk] = h;
        lo[(size_t)n * K + kk] = l;
    }
}

// ============ HMMA split-bf16 GEMM ==============
// EPI_NONE/EPI_RES: write fp32 C (+res). EPI_GELU: write gelu(out) as split bf16.
enum { EPI_NONE = 0, EPI_RES = 1, EPI_GELU = 2 };

template<int EPI>
__global__ __launch_bounds__(256, 2)
void gemm_mma(const __nv_bfloat16* __restrict__ a_hi, const __nv_bfloat16* __restrict__ a_lo,
              const __nv_bfloat16* __restrict__ w_hi, const __nv_bfloat16* __restrict__ w_lo,
              const float* __restrict__ bias, const float* __restrict__ res,
              float* __restrict__ C, __nv_bfloat16* __restrict__ Chi,
              __nv_bfloat16* __restrict__ Clo, int M, int N, int K)
{
    extern __shared__ __align__(16) char smem[];
    const uint32_t sb = smem_u32(smem);
    const int tid = threadIdx.x;
    const int lane = tid & 31, wid = tid >> 5;
    const int wm = wid & 3, wn = wid >> 2;          // 4 x 2 warp grid
    const int bm = blockIdx.y * 128, bn = blockIdx.x * 128;

    // ---- cp.async geometry: thread -> (row, 2 chunks of 16B) ----
    const int crow = tid & 127;
    const int cch = (tid >> 7) * 2;                 // 0 or 2
    const char* gsrc[4];
    gsrc[0] = (const char*)a_hi + (size_t)(bm + crow) * K * 2;
    gsrc[1] = (const char*)a_lo + (size_t)(bm + crow) * K * 2;
    gsrc[2] = (const char*)w_hi + (size_t)(bn + crow) * K * 2;
    gsrc[3] = (const char*)w_lo + (size_t)(bn + crow) * K * 2;
    uint32_t sdst[4];
    #pragma unroll
    for (int op = 0; op < 4; op++)
        sdst[op] = sb + op * OPB + crow * 80 + cch * 16;

    // ---- ldmatrix per-thread base addresses (stage 0) ----
    const uint32_t a_off = (uint32_t)((wm * 32 + (lane & 15)) * 80 + ((lane >> 4) & 1) * 16);
    const uint32_t b_off = (uint32_t)((wn * 64 + ((lane >> 4) << 3) + (lane & 7)) * 80 + ((lane >> 3) & 1) * 16);
    const uint32_t aH = sb + a_off;                 // A_hi
    const uint32_t aL = sb + OPB + a_off;           // A_lo
    const uint32_t bH = sb + 2 * OPB + b_off;       // B_hi
    const uint32_t bL = sb + 3 * OPB + b_off;       // B_lo

    float acc[2][8][4];
    #pragma unroll
    for (int mf = 0; mf < 2; mf++)
        #pragma unroll
        for (int nf = 0; nf < 8; nf++)
            #pragma unroll
            for (int e = 0; e < 4; e++) acc[mf][nf][e] = 0.f;

    const int NC = K >> 5;

    // prologue: stage 0 (k-chunk 0)
    #pragma unroll
    for (int op = 0; op < 4; op++) {
        cpasync16(sdst[op], gsrc[op] + (cch + 0) * 16);
        cpasync16(sdst[op] + 16, gsrc[op] + (cch + 1) * 16);
    }
    asm volatile("cp.async.commit_group;" ::: "memory");

    for (int c = 0; c < NC; c++) {
        if (c + 1 < NC) {
            const uint32_t so = (uint32_t)(((c + 1) & 1) * STAGE);
            const size_t go = (size_t)(c + 1) * 64;
            #pragma unroll
            for (int op = 0; op < 4; op++) {
                cpasync16(sdst[op] + so, gsrc[op] + go + (cch + 0) * 16);
                cpasync16(sdst[op] + so + 16, gsrc[op] + go + (cch + 1) * 16);
            }
            asm volatile("cp.async.commit_group;" ::: "memory");
            asm volatile("cp.async.wait_group 1;" ::: "memory");
        } else {
            asm volatile("cp.async.wait_group 0;" ::: "memory");
        }
        __syncthreads();

        const uint32_t so = (uint32_t)((c & 1) * STAGE);
        #pragma unroll
        for (int ks = 0; ks < 2; ks++) {
            uint32_t ah[2][4], al[2][4];
            #pragma unroll
            for (int mf = 0; mf < 2; mf++) {
                ldm4(ah[mf], aH + so + mf * (16 * 80) + ks * 32);
                ldm4(al[mf], aL + so + mf * (16 * 80) + ks * 32);
            }
            #pragma unroll
            for (int p = 0; p < 4; p++) {
                uint32_t bh[4], bl[4];
                ldm4(bh, bH + so + p * (16 * 80) + ks * 32);
                ldm4(bl, bL + so + p * (16 * 80) + ks * 32);
                #pragma unroll
                for (int mf = 0; mf < 2; mf++) {
                    mma16816(acc[mf][2 * p],     ah[mf], bh[0], bh[1]);
                    mma16816(acc[mf][2 * p + 1], ah[mf], bh[2], bh[3]);
                    mma16816(acc[mf][2 * p],     al[mf], bh[0], bh[1]);
                    mma16816(acc[mf][2 * p + 1], al[mf], bh[2], bh[3]);
                    mma16816(acc[mf][2 * p],     ah[mf], bl[0], bl[1]);
                    mma16816(acc[mf][2 * p + 1], ah[mf], bl[2], bl[3]);
                }
            }
        }
        __syncthreads();
    }

    // ---- epilogue ----
    const int r0 = bm + wm * 32 + (lane >> 2);
    const int cb = bn + wn * 64 + (lane & 3) * 2;
    #pragma unroll
    for (int mf = 0; mf < 2; mf++) {
        #pragma unroll
        for (int nf = 0; nf < 8; nf++) {
            const int row = r0 + mf * 16;
            const int col = cb + nf * 8;
            float2 bv = *(const float2*)(bias + col);
            float v0 = acc[mf][nf][0] + bv.x, v1 = acc[mf][nf][1] + bv.y;
            float v2 = acc[mf][nf][2] + bv.x, v3 = acc[mf][nf][3] + bv.y;
            if (EPI == EPI_RES) {
                float2 ra = *(const float2*)(res + (size_t)row * N + col);
                float2 rb = *(const float2*)(res + (size_t)(row + 8) * N + col);
                v0 += ra.x; v1 += ra.y; v2 += rb.x; v3 += rb.y;
            }
            if (EPI == EPI_GELU) {
                v0 = 0.5f * v0 * (1.f + erff(v0 * 0.70710678118654752f));
                v1 = 0.5f * v1 * (1.f + erff(v1 * 0.70710678118654752f));
                v2 = 0.5f * v2 * (1.f + erff(v2 * 0.70710678118654752f));
                v3 = 0.5f * v3 * (1.f + erff(v3 * 0.70710678118654752f));
                __nv_bfloat16 h0, h1, h2, h3, l0, l1, l2, l3;
                split1(v0, h0, l0); split1(v1, h1, l1);
                split1(v2, h2, l2); split1(v3, h3, l3);
                *(__nv_bfloat162*)(Chi + (size_t)row * N + col) = __nv_bfloat162(h0, h1);
                *(__nv_bfloat162*)(Clo + (size_t)row * N + col) = __nv_bfloat162(l0, l1);
                *(__nv_bfloat162*)(Chi + (size_t)(row + 8) * N + col) = __nv_bfloat162(h2, h3);
                *(__nv_bfloat162*)(Clo + (size_t)(row + 8) * N + col) = __nv_bfloat162(l2, l3);
            } else {
                *(float2*)(C + (size_t)row * N + col) = make_float2(v0, v1);
                *(float2*)(C + (size_t)(row + 8) * N + col) = make_float2(v2, v3);
            }
        }
    }
}

// ============ scores = (Q K^T)*scale — 128x128 tiles, f32x2 ==================
__global__ __launch_bounds__(256, 2)
void attn_scores(const float* __restrict__ q, const float* __restrict__ k,
                 float* __restrict__ sc)
{
    __shared__ __align__(16) float Qs[32][132];
    __shared__ __align__(16) float Ks[32][132];
    const int bh = blockIdx.z;
    const int b = bh >> 3, h = bh & 7;
    const int s1_0 = blockIdx.y * 128, s2_0 = blockIdx.x * 128;
    const int tid = threadIdx.x;
    const int tx = tid & 15, ty = tid >> 4;

    unsigned long long acc2[4][8];
    #pragma unroll
    for (int p = 0; p < 4; p++)
        #pragma unroll
        for (int j = 0; j < 8; j++) acc2[p][j] = 0ull;

    #pragma unroll
    for (int kt = 0; kt < 2; kt++) {
        for (int t = tid; t < 1024; t += 256) {
            int r = t >> 3, c = (t & 7) * 4;
            float4 qv = *(const float4*)(q + ((size_t)(b * Ss + s1_0 + r)) * Dd + h * DH + kt * 32 + c);
            float4 kv = *(const float4*)(k + ((size_t)(b * Ss + s2_0 + r)) * Dd + h * DH + kt * 32 + c);
            Qs[c + 0][r] = qv.x; Qs[c + 1][r] = qv.y; Qs[c + 2][r] = qv.z; Qs[c + 3][r] = qv.w;
            Ks[c + 0][r] = kv.x; Ks[c + 1][r] = kv.y; Ks[c + 2][r] = kv.z; Ks[c + 3][r] = kv.w;
        }
        __syncthreads();
        #pragma unroll
        for (int kk = 0; kk < 32; kk++) {
            ulonglong2 a01 = *(const ulonglong2*)&Qs[kk][ty * 8];
            ulonglong2 a23 = *(const ulonglong2*)&Qs[kk][ty * 8 + 4];
            unsigned long long ap[4] = { a01.x, a01.y, a23.x, a23.y };
            float4 q0 = *(const float4*)&Ks[kk][tx * 8];
            float4 q1 = *(const float4*)&Ks[kk][tx * 8 + 4];
            unsigned long long bd[8] = { dupf(q0.x), dupf(q0.y), dupf(q0.z), dupf(q0.w),
                                         dupf(q1.x), dupf(q1.y), dupf(q1.z), dupf(q1.w) };
            #pragma unroll
            for (int p = 0; p < 4; p++)
                #pragma unroll
                for (int j = 0; j < 8; j++)
                    ffma2(acc2[p][j], ap[p], bd[j]);
        }
        __syncthreads();
    }

    const float scale = 0.125f;
    #pragma unroll
    for (int p = 0; p < 4; p++) {
        int row0 = s1_0 + ty * 8 + 2 * p;
        #pragma unroll
        for (int j = 0; j < 8; j++) {
            int col = s2_0 + tx * 8 + j;
            float2 c = unpack2(acc2[p][j]);
            sc[((size_t)bh * Ss + row0) * Ss + col] = c.x * scale;
            sc[((size_t)bh * Ss + row0 + 1) * Ss + col] = c.y * scale;
        }
    }
}

// ============ softmax with key-padding mask ==================================
__global__ __launch_bounds__(256)
void softmax_mask(float* __restrict__ sc, const int* __restrict__ mask)
{
    __shared__ float red[8];
    const size_t row = blockIdx.x;
    const int b = (int)(blockIdx.x / (Hh * Ss));
    float* p = sc + row * Ss;
    const int* mr = mask + (size_t)b * Ss;
    const int tid = threadIdx.x;
    const float NEG = __int_as_float(0xff800000);

    float v0 = mr[tid] ? p[tid] : NEG;
    float v1 = mr[tid + 256] ? p[tid + 256] : NEG;

    float m = fmaxf(v0, v1);
    #pragma unroll
    for (int o = 16; o; o >>= 1) m = fmaxf(m, __shfl_xor_sync(0xffffffffu, m, o));
    if ((tid & 31) == 0) red[tid >> 5] = m;
    __syncthreads();
    m = red[0];
    #pragma unroll
    for (int i = 1; i < 8; i++) m = fmaxf(m, red[i]);
    __syncthreads();

    float e0 = __expf(v0 - m), e1 = __expf(v1 - m);
    float s = e0 + e1;
    #pragma unroll
    for (int o = 16; o; o >>= 1) s += __shfl_xor_sync(0xffffffffu, s, o);
    if ((tid & 31) == 0) red[tid >> 5] = s;
    __syncthreads();
    s = red[0] + red[1] + red[2] + red[3] + red[4] + red[5] + red[6] + red[7];

    float inv = 1.f / s;
    p[tid] = e0 * inv;
    p[tid + 256] = e1 * inv;
}

// ============ ctx = P @ V — 128x64 tiles, f32x2; writes split bf16 ===========
__global__ __launch_bounds__(128, 4)
void attn_ctx(const float* __restrict__ sc, const float* __restrict__ v,
              __nv_bfloat16* __restrict__ ohi, __nv_bfloat16* __restrict__ olo)
{
    __shared__ __align__(16) float Ws[32][132];
    __shared__ __align__(16) float Vs[32][64];
    const int bh = blockIdx.z;
    const int b = bh >> 3, h = bh & 7;
    const int s1_0 = blockIdx.y * 128;
    const int tid = threadIdx.x;
    const int tx = tid & 7, ty = tid >> 3;

    unsigned long long acc2[4][8];
    #pragma unroll
    for (int p = 0; p < 4; p++)
        #pragma unroll
        for (int j = 0; j < 8; j++) acc2[p][j] = 0ull;

    for (int k0 = 0; k0 < Ss; k0 += 32) {
        for (int t = tid; t < 1024; t += 128) {
            int r = t >> 3, c = (t & 7) * 4;
            float4 wv = *(const float4*)(sc + ((size_t)bh * Ss + s1_0 + r) * Ss + k0 + c);
            Ws[c + 0][r] = wv.x; Ws[c + 1][r] = wv.y; Ws[c + 2][r] = wv.z; Ws[c + 3][r] = wv.w;
        }
        for (int t = tid; t < 512; t += 128) {
            int r = t >> 4, c = (t & 15) * 4;
            float4 vv = *(const float4*)(v + ((size_t)(b * Ss + k0 + r)) * Dd + h * DH + c);
            *(float4*)&Vs[r][c] = vv;
        }
        __syncthreads();
        #pragma unroll
        for (int kk = 0; kk < 32; kk++) {
            ulonglong2 a01 = *(const ulonglong2*)&Ws[kk][ty * 8];
            ulonglong2 a23 = *(const ulonglong2*)&Ws[kk][ty * 8 + 4];
            unsigned long long ap[4] = { a01.x, a01.y, a23.x, a23.y };
            float4 q0 = *(const float4*)&Vs[kk][tx * 8];
            float4 q1 = *(const float4*)&Vs[kk][tx * 8 + 4];
            unsigned long long bd[8] = { dupf(q0.x), dupf(q0.y), dupf(q0.z), dupf(q0.w),
                                         dupf(q1.x), dupf(q1.y), dupf(q1.z), dupf(q1.w) };
            #pragma unroll
            for (int p = 0; p < 4; p++)
                #pragma unroll
                for (int j = 0; j < 8; j++)
                    ffma2(acc2[p][j], ap[p], bd[j]);
        }
        __syncthreads();
    }

    #pragma unroll
    for (int p = 0; p < 4; p++) {
        int row0 = s1_0 + ty * 8 + 2 * p;
        #pragma unroll
        for (int j = 0; j < 8; j++) {
            int col = h * DH + tx * 8 + j;
            float2 c = unpack2(acc2[p][j]);
            __nv_bfloat16 h0, l0, h1, l1;
            split1(c.x, h0, l0);
            split1(c.y, h1, l1);
            ohi[((size_t)(b * Ss + row0)) * Dd + col] = h0;
            olo[((size_t)(b * Ss + row0)) * Dd + col] = l0;
            ohi[((size_t)(b * Ss + row0 + 1)) * Dd + col] = h1;
            olo[((size_t)(b * Ss + row0 + 1)) * Dd + col] = l1;
        }
    }
}

// ============ layernorm (+ optional fused split output) ======================
__device__ __forceinline__ float block_sum_128(float v, float* red)
{
    #pragma unroll
    for (int o = 16; o; o >>= 1) v += __shfl_xor_sync(0xffffffffu, v, o);
    if ((threadIdx.x & 31) == 0) red[threadIdx.x >> 5] = v;
    __syncthreads();
    v = red[0] + red[1] + red[2] + red[3];
    __syncthreads();
    return v;
}

__device__ __forceinline__ void write_split4(__nv_bfloat16* hi, __nv_bfloat16* lo,
                                             size_t base, float4 o)
{
    __nv_bfloat16 h0, h1, h2, h3, l0, l1, l2, l3;
    split1(o.x, h0, l0); split1(o.y, h1, l1); split1(o.z, h2, l2); split1(o.w, h3, l3);
    *(__nv_bfloat162*)(hi + base) = __nv_bfloat162(h0, h1);
    *(__nv_bfloat162*)(hi + base + 2) = __nv_bfloat162(h2, h3);
    *(__nv_bfloat162*)(lo + base) = __nv_bfloat162(l0, l1);
    *(__nv_bfloat162*)(lo + base + 2) = __nv_bfloat162(l2, l3);
}

__global__ __launch_bounds__(128)
void ln_kernel(const float* __restrict__ in, float* __restrict__ out,
               const float* __restrict__ gamma, const float* __restrict__ beta,
               int vid_mode, __nv_bfloat16* __restrict__ hi, __nv_bfloat16* __restrict__ lo)
{
    __shared__ float red[4];
    const int r = blockIdx.x, tid = threadIdx.x;
    float4 v = *(const float4*)(in + (size_t)r * Dd + tid * 4);
    float s = block_sum_128(v.x + v.y + v.z + v.w, red);
    float mean = s * (1.f / Dd);
    float d0 = v.x - mean, d1 = v.y - mean, d2 = v.z - mean, d3 = v.w - mean;
    float sq = block_sum_128(d0 * d0 + d1 * d1 + d2 * d2 + d3 * d3, red);
    float inv = rsqrtf(sq * (1.f / Dd) + 1e-12f);
    int orow = vid_mode ? ((r / Tt) * Ss + Qn + (r % Tt)) : r;
    float4 gg = *(const float4*)(gamma + tid * 4);
    float4 bb = *(const float4*)(beta + tid * 4);
    float4 o;
    o.x = d0 * inv * gg.x + bb.x;
    o.y = d1 * inv * gg.y + bb.y;
    o.z = d2 * inv * gg.z + bb.z;
    o.w = d3 * inv * gg.w + bb.w;
    *(float4*)(out + (size_t)orow * Dd + tid * 4) = o;
    if (hi) write_split4(hi, lo, (size_t)orow * Dd + tid * 4, o);
}

__global__ __launch_bounds__(128)
void posmod_ln(const float* __restrict__ question, const float* __restrict__ pos,
               const float* __restrict__ mod, const float* __restrict__ gamma,
               const float* __restrict__ beta,
               __nv_bfloat16* __restrict__ hi, __nv_bfloat16* __restrict__ lo)
{
    __shared__ float red[4];
    const int r = blockIdx.x;
    const int b = r / Ss, s = r % Ss;
    const int tid = threadIdx.x;
    float4 xv;
    if (s < Qn) xv = *(const float4*)(question + ((size_t)b * Qn + s) * Dd + tid * 4);
    else        xv = *(const float4*)(g_x + (size_t)r * Dd + tid * 4);
    float4 pv = *(const float4*)(pos + (size_t)s * Dd + tid * 4);
    const float* mrow = mod + (s < Qn ? 0 : Dd);
    float4 mv = *(const float4*)(mrow + tid * 4);
    xv.x += pv.x + mv.x; xv.y += pv.y + mv.y; xv.z += pv.z + mv.z; xv.w += pv.w + mv.w;

    float su = block_sum_128(xv.x + xv.y + xv.z + xv.w, red);
    float mean = su * (1.f / Dd);
    float d0 = xv.x - mean, d1 = xv.y - mean, d2 = xv.z - mean, d3 = xv.w - mean;
    float sq = block_sum_128(d0 * d0 + d1 * d1 + d2 * d2 + d3 * d3, red);
    float inv = rsqrtf(sq * (1.f / Dd) + 1e-12f);
    float4 gg = *(const float4*)(gamma + tid * 4);
    float4 bb = *(const float4*)(beta + tid * 4);
    float4 o;
    o.x = d0 * inv * gg.x + bb.x;
    o.y = d1 * inv * gg.y + bb.y;
    o.z = d2 * inv * gg.z + bb.z;
    o.w = d3 * inv * gg.w + bb.w;
    *(float4*)(g_x + (size_t)r * Dd + tid * 4) = o;
    write_split4(hi, lo, (size_t)r * Dd + tid * 4, o);
}

// -------------------------------- launch ---------------------------------------
extern "C" void kernel_launch(void* const* d_in, const int* in_sizes, int n_in,
                              void* d_out, int out_size)
{
    const float* video    = (const float*)d_in[0];
    const float* question = (const float*)d_in[1];
    const int*   mask     = (const int*)d_in[2];
    const float* pos_emb  = (const float*)d_in[3];
    const float* mod_emb  = (const float*)d_in[4];
    const float* Wv   = (const float*)d_in[5];
    const float* bv   = (const float*)d_in[6];
    const float* nv_g = (const float*)d_in[7];
    const float* nv_b = (const float*)d_in[8];
    const float* emb_g = (const float*)d_in[9];
    const float* emb_b = (const float*)d_in[10];
    const float* Wq  = (const float*)d_in[11];
    const float* bq  = (const float*)d_in[12];
    const float* Wk  = (const float*)d_in[13];
    const float* bk  = (const float*)d_in[14];
    const float* Wva = (const float*)d_in[15];
    const float* bva = (const float*)d_in[16];
    const float* Wo  = (const float*)d_in[17];
    const float* bo  = (const float*)d_in[18];
    const float* ln1g = (const float*)d_in[19];
    const float* ln1b = (const float*)d_in[20];
    const float* W1  = (const float*)d_in[21];
    const float* b1  = (const float*)d_in[22];
    const float* W2  = (const float*)d_in[23];
    const float* b2  = (const float*)d_in[24];
    const float* ln2g = (const float*)d_in[25];
    const float* ln2b = (const float*)d_in[26];
    float* out = (float*)d_out;

    float *x, *tmp, *q, *k, *v, *sc;
    __nv_bfloat16 *gah, *gal, *gbh, *gbl, *wh, *wl;
    cudaGetSymbolAddress((void**)&x,    g_x);
    cudaGetSymbolAddress((void**)&tmp,  g_tmp);
    cudaGetSymbolAddress((void**)&q,    g_q);
    cudaGetSymbolAddress((void**)&k,    g_k);
    cudaGetSymbolAddress((void**)&v,    g_v);
    cudaGetSymbolAddress((void**)&sc,   g_sc);
    cudaGetSymbolAddress((void**)&gah,  ga_hi);
    cudaGetSymbolAddress((void**)&gal,  ga_lo);
    cudaGetSymbolAddress((void**)&gbh,  gb_hi);
    cudaGetSymbolAddress((void**)&gbl,  gb_lo);
    cudaGetSymbolAddress((void**)&wh,   gw_hi);
    cudaGetSymbolAddress((void**)&wl,   gw_lo);

    cudaFuncSetAttribute(gemm_mma<EPI_NONE>, cudaFuncAttributeMaxDynamicSharedMemorySize, SMEM_MMA);
    cudaFuncSetAttribute(gemm_mma<EPI_RES>,  cudaFuncAttributeMaxDynamicSharedMemorySize, SMEM_MMA);
    cudaFuncSetAttribute(gemm_mma<EPI_GELU>, cudaFuncAttributeMaxDynamicSharedMemorySize, SMEM_MMA);

    auto tsplit = [&](const float* W, int K, int N) {
        transpose_split<<<dim3(N / 32, K / 32), dim3(32, 8)>>>(W, wh, wl, K, N);
    };

    // video projection + LN into x[:, Q:, :]
    {
        size_t n4 = (size_t)BT * FDd / 4;
        split_kernel<<<(unsigned)((n4 + 255) / 256), 256>>>(video, gah, gal, n4);
    }
    tsplit(Wv, FDd, Dd);
    gemm_mma<EPI_NONE><<<dim3(Dd / 128, BT / 128), 256, SMEM_MMA>>>(gah, gal, wh, wl, bv, nullptr, tmp, nullptr, nullptr, BT, Dd, FDd);
    ln_kernel<<<BT, 128>>>(tmp, x, nv_g, nv_b, 1, nullptr, nullptr);
    posmod_ln<<<BS, 128>>>(question, pos_emb, mod_emb, emb_g, emb_b, gbh, gbl);

    for (int i = 0; i < NL; i++) {
        const size_t WO = (size_t)i * Dd * Dd;
        tsplit(Wq + WO, Dd, Dd);
        gemm_mma<EPI_NONE><<<dim3(Dd / 128, BS / 128), 256, SMEM_MMA>>>(gbh, gbl, wh, wl, bq + i * Dd, nullptr, q, nullptr, nullptr, BS, Dd, Dd);
        tsplit(Wk + WO, Dd, Dd);
        gemm_mma<EPI_NONE><<<dim3(Dd / 128, BS / 128), 256, SMEM_MMA>>>(gbh, gbl, wh, wl, bk + i * Dd, nullptr, k, nullptr, nullptr, BS, Dd, Dd);
        tsplit(Wva + WO, Dd, Dd);
        gemm_mma<EPI_NONE><<<dim3(Dd / 128, BS / 128), 256, SMEM_MMA>>>(gbh, gbl, wh, wl, bva + i * Dd, nullptr, v, nullptr, nullptr, BS, Dd, Dd);

        attn_scores<<<dim3(Ss / 128, Ss / 128, Bb * Hh), 256>>>(q, k, sc);
        softmax_mask<<<Bb * Hh * Ss, 256>>>(sc, mask);
        attn_ctx<<<dim3(1, Ss / 128, Bb * Hh), 128>>>(sc, v, gbh, gbl);   // ctx -> gb (split)

        tsplit(Wo + WO, Dd, Dd);
        gemm_mma<EPI_RES><<<dim3(Dd / 128, BS / 128), 256, SMEM_MMA>>>(gbh, gbl, wh, wl, bo + i * Dd, x, tmp, nullptr, nullptr, BS, Dd, Dd);
        ln_kernel<<<BS, 128>>>(tmp, x, ln1g + i * Dd, ln1b + i * Dd, 0, gbh, gbl);

        tsplit(W1 + (size_t)i * Dd * FFf, Dd, FFf);
        gemm_mma<EPI_GELU><<<dim3(FFf / 128, BS / 128), 256, SMEM_MMA>>>(gbh, gbl, wh, wl, b1 + i * FFf, nullptr, nullptr, gah, gal, BS, FFf, Dd);

        tsplit(W2 + (size_t)i * FFf * Dd, FFf, Dd);
        gemm_mma<EPI_RES><<<dim3(Dd / 128, BS / 128), 256, SMEM_MMA>>>(gah, gal, wh, wl, b2 + i * Dd, x, tmp, nullptr, nullptr, BS, Dd, FFf);

        if (i == NL - 1) {
            ln_kernel<<<BS, 128>>>(tmp, out, ln2g + i * Dd, ln2b + i * Dd, 0, nullptr, nullptr);
        } else {
            ln_kernel<<<BS, 128>>>(tmp, x, ln2g + i * Dd, ln2b + i * Dd, 0, gbh, gbl);
        }
    }
}

// round 9
// speedup vs baseline: 2.0493x; 1.2103x over previous
#include <cuda_runtime.h>
#include <cuda_bf16.h>
#include <math.h>
#include <stdint.h>

#define Bb 64
#define Qn 64
#define Tt 448
#define Dd 512
#define FDd 1024
#define Hh 8
#define NL 2
#define FFf 2048
#define Ss 512
#define DH 64
#define BS (Bb*Ss)
#define BT (Bb*Tt)

// ---------------- scratch (device globals: allocation-free) ----------------
__device__ float g_x[(size_t)BS*Dd];
__device__ float g_tmp[(size_t)BS*Dd];
__device__ float g_sc[(size_t)Bb*Hh*Ss*Ss];
// split-bf16 buffers
__device__ __nv_bfloat16 ga_hi[(size_t)BS*FFf];
__device__ __nv_bfloat16 ga_lo[(size_t)BS*FFf];
__device__ __nv_bfloat16 gb_hi[(size_t)BS*Dd];
__device__ __nv_bfloat16 gb_lo[(size_t)BS*Dd];
__device__ __nv_bfloat16 gw_hi[(size_t)FFf*Dd];
__device__ __nv_bfloat16 gw_lo[(size_t)FFf*Dd];
__device__ __nv_bfloat16 g_qh[(size_t)BS*Dd];
__device__ __nv_bfloat16 g_ql[(size_t)BS*Dd];
__device__ __nv_bfloat16 g_kh[(size_t)BS*Dd];
__device__ __nv_bfloat16 g_kl[(size_t)BS*Dd];
__device__ __nv_bfloat16 g_vth[(size_t)BS*Dd];   // [B*H, 64, S]
__device__ __nv_bfloat16 g_vtl[(size_t)BS*Dd];
__device__ __nv_bfloat16 g_ph[(size_t)Bb*Hh*Ss*Ss];
__device__ __nv_bfloat16 g_pl[(size_t)Bb*Hh*Ss*Ss];

// ---------------- small helpers ----------------
__device__ __forceinline__ void split1(float v, __nv_bfloat16& h, __nv_bfloat16& l) {
    h = __float2bfloat16(v);
    l = __float2bfloat16(v - __bfloat162float(h));
}
__device__ __forceinline__ uint32_t smem_u32(const void* p) {
    uint32_t a;
    asm("{ .reg .u64 t; cvta.to.shared.u64 t, %1; cvt.u32.u64 %0, t; }" : "=r"(a) : "l"(p));
    return a;
}
__device__ __forceinline__ void ldm4(uint32_t* r, uint32_t addr) {
    asm volatile("ldmatrix.sync.aligned.m8n8.x4.shared.b16 {%0,%1,%2,%3}, [%4];"
                 : "=r"(r[0]), "=r"(r[1]), "=r"(r[2]), "=r"(r[3]) : "r"(addr));
}
__device__ __forceinline__ void mma16816(float* c, const uint32_t* a, uint32_t b0, uint32_t b1) {
    asm volatile("mma.sync.aligned.m16n8k16.row.col.f32.bf16.bf16.f32 "
                 "{%0,%1,%2,%3}, {%4,%5,%6,%7}, {%8,%9}, {%0,%1,%2,%3};"
                 : "+f"(c[0]), "+f"(c[1]), "+f"(c[2]), "+f"(c[3])
                 : "r"(a[0]), "r"(a[1]), "r"(a[2]), "r"(a[3]), "r"(b0), "r"(b1));
}
__device__ __forceinline__ void cpasync16(uint32_t dst, const void* src) {
    asm volatile("cp.async.cg.shared.global [%0], [%1], 16;" :: "r"(dst), "l"(src));
}

// gemm smem geometry
#define OPB   10240
#define STAGE 40960
#define SMEM_MMA (2 * STAGE)
// scores smem geometry
#define SPITCH 144
#define STILE  (128 * SPITCH)
#define SMEM_SC (4 * STILE)
// ctx smem geometry
#define CPITCH 80
#define CP_TILE (128 * CPITCH)
#define CV_TILE (64 * CPITCH)
#define CSTAGE (2 * CP_TILE + 2 * CV_TILE)
#define SMEM_CTX (2 * CSTAGE)

// ============ split conversion (video input only) ============
__global__ __launch_bounds__(256)
void split_kernel(const float* __restrict__ in, __nv_bfloat16* __restrict__ hi,
                  __nv_bfloat16* __restrict__ lo, size_t n4)
{
    size_t i = (size_t)blockIdx.x * 256 + threadIdx.x;
    if (i >= n4) return;
    float4 v = ((const float4*)in)[i];
    __nv_bfloat16 h0, h1, h2, h3, l0, l1, l2, l3;
    split1(v.x, h0, l0); split1(v.y, h1, l1); split1(v.z, h2, l2); split1(v.w, h3, l3);
    ((__nv_bfloat162*)hi)[2 * i] = __nv_bfloat162(h0, h1);
    ((__nv_bfloat162*)hi)[2 * i + 1] = __nv_bfloat162(h2, h3);
    ((__nv_bfloat162*)lo)[2 * i] = __nv_bfloat162(l0, l1);
    ((__nv_bfloat162*)lo)[2 * i + 1] = __nv_bfloat162(l2, l3);
}

// W[K][N] fp32 -> out[N][K] split bf16
__global__ __launch_bounds__(256)
void transpose_split(const float* __restrict__ W, __nv_bfloat16* __restrict__ hi,
                     __nv_bfloat16* __restrict__ lo, int K, int N)
{
    __shared__ float t[32][33];
    const int n0 = blockIdx.x * 32, k0 = blockIdx.y * 32;
    const int tx = threadIdx.x, ty = threadIdx.y;
    #pragma unroll
    for (int j = 0; j < 4; j++)
        t[ty + j * 8][tx] = W[(size_t)(k0 + ty + j * 8) * N + n0 + tx];
    __syncthreads();
    #pragma unroll
    for (int j = 0; j < 4; j++) {
        int n = n0 + ty + j * 8, kk = k0 + tx;
        __nv_bfloat16 h, l;
        split1(t[tx][ty + j * 8], h, l);
        hi[(size_t)n * K + kk] = h;
        lo[(size_t)n * K + kk] = l;
    }
}

// ============ HMMA split-bf16 GEMM ==============
// 0: fp32 C    1: fp32 C + res    2: gelu -> split bf16
// 3: split bf16 (normal layout)   4: split bf16 transposed per-head [B*H,64,S]
enum { EPI_NONE = 0, EPI_RES = 1, EPI_GELU = 2, EPI_SPLIT = 3, EPI_SPLITT = 4 };

template<int EPI>
__global__ __launch_bounds__(256, 2)
void gemm_mma(const __nv_bfloat16* __restrict__ a_hi, const __nv_bfloat16* __restrict__ a_lo,
              const __nv_bfloat16* __restrict__ w_hi, const __nv_bfloat16* __restrict__ w_lo,
              const float* __restrict__ bias, const float* __restrict__ res,
              float* __restrict__ C, __nv_bfloat16* __restrict__ Chi,
              __nv_bfloat16* __restrict__ Clo, int M, int N, int K)
{
    extern __shared__ __align__(16) char smem[];
    const uint32_t sb = smem_u32(smem);
    const int tid = threadIdx.x;
    const int lane = tid & 31, wid = tid >> 5;
    const int wm = wid & 3, wn = wid >> 2;
    const int bm = blockIdx.y * 128, bn = blockIdx.x * 128;

    const int crow = tid & 127;
    const int cch = (tid >> 7) * 2;
    const char* gsrc[4];
    gsrc[0] = (const char*)a_hi + (size_t)(bm + crow) * K * 2;
    gsrc[1] = (const char*)a_lo + (size_t)(bm + crow) * K * 2;
    gsrc[2] = (const char*)w_hi + (size_t)(bn + crow) * K * 2;
    gsrc[3] = (const char*)w_lo + (size_t)(bn + crow) * K * 2;
    uint32_t sdst[4];
    #pragma unroll
    for (int op = 0; op < 4; op++)
        sdst[op] = sb + op * OPB + crow * 80 + cch * 16;

    const uint32_t a_off = (uint32_t)((wm * 32 + (lane & 15)) * 80 + ((lane >> 4) & 1) * 16);
    const uint32_t b_off = (uint32_t)((wn * 64 + ((lane >> 4) << 3) + (lane & 7)) * 80 + ((lane >> 3) & 1) * 16);
    const uint32_t aH = sb + a_off;
    const uint32_t aL = sb + OPB + a_off;
    const uint32_t bH = sb + 2 * OPB + b_off;
    const uint32_t bL = sb + 3 * OPB + b_off;

    float acc[2][8][4];
    #pragma unroll
    for (int mf = 0; mf < 2; mf++)
        #pragma unroll
        for (int nf = 0; nf < 8; nf++)
            #pragma unroll
            for (int e = 0; e < 4; e++) acc[mf][nf][e] = 0.f;

    const int NC = K >> 5;

    #pragma unroll
    for (int op = 0; op < 4; op++) {
        cpasync16(sdst[op], gsrc[op] + (cch + 0) * 16);
        cpasync16(sdst[op] + 16, gsrc[op] + (cch + 1) * 16);
    }
    asm volatile("cp.async.commit_group;" ::: "memory");

    for (int c = 0; c < NC; c++) {
        if (c + 1 < NC) {
            const uint32_t so = (uint32_t)(((c + 1) & 1) * STAGE);
            const size_t go = (size_t)(c + 1) * 64;
            #pragma unroll
            for (int op = 0; op < 4; op++) {
                cpasync16(sdst[op] + so, gsrc[op] + go + (cch + 0) * 16);
                cpasync16(sdst[op] + so + 16, gsrc[op] + go + (cch + 1) * 16);
            }
            asm volatile("cp.async.commit_group;" ::: "memory");
            asm volatile("cp.async.wait_group 1;" ::: "memory");
        } else {
            asm volatile("cp.async.wait_group 0;" ::: "memory");
        }
        __syncthreads();

        const uint32_t so = (uint32_t)((c & 1) * STAGE);
        #pragma unroll
        for (int ks = 0; ks < 2; ks++) {
            uint32_t ah[2][4], al[2][4];
            #pragma unroll
            for (int mf = 0; mf < 2; mf++) {
                ldm4(ah[mf], aH + so + mf * (16 * 80) + ks * 32);
                ldm4(al[mf], aL + so + mf * (16 * 80) + ks * 32);
            }
            #pragma unroll
            for (int p = 0; p < 4; p++) {
                uint32_t bh[4], bl[4];
                ldm4(bh, bH + so + p * (16 * 80) + ks * 32);
                ldm4(bl, bL + so + p * (16 * 80) + ks * 32);
                #pragma unroll
                for (int mf = 0; mf < 2; mf++) {
                    mma16816(acc[mf][2 * p],     ah[mf], bh[0], bh[1]);
                    mma16816(acc[mf][2 * p + 1], ah[mf], bh[2], bh[3]);
                    mma16816(acc[mf][2 * p],     al[mf], bh[0], bh[1]);
                    mma16816(acc[mf][2 * p + 1], al[mf], bh[2], bh[3]);
                    mma16816(acc[mf][2 * p],     ah[mf], bl[0], bl[1]);
                    mma16816(acc[mf][2 * p + 1], ah[mf], bl[2], bl[3]);
                }
            }
        }
        __syncthreads();
    }

    // ---- epilogue ----
    const int r0 = bm + wm * 32 + (lane >> 2);
    const int cb = bn + wn * 64 + (lane & 3) * 2;
    #pragma unroll
    for (int mf = 0; mf < 2; mf++) {
        #pragma unroll
        for (int nf = 0; nf < 8; nf++) {
            const int row = r0 + mf * 16;
            const int col = cb + nf * 8;
            float2 bv = *(const float2*)(bias + col);
            float v0 = acc[mf][nf][0] + bv.x, v1 = acc[mf][nf][1] + bv.y;
            float v2 = acc[mf][nf][2] + bv.x, v3 = acc[mf][nf][3] + bv.y;
            if (EPI == EPI_RES) {
                float2 ra = *(const float2*)(res + (size_t)row * N + col);
                float2 rb = *(const float2*)(res + (size_t)(row + 8) * N + col);
                v0 += ra.x; v1 += ra.y; v2 += rb.x; v3 += rb.y;
            }
            if (EPI == EPI_GELU) {
                v0 = 0.5f * v0 * (1.f + erff(v0 * 0.70710678118654752f));
                v1 = 0.5f * v1 * (1.f + erff(v1 * 0.70710678118654752f));
                v2 = 0.5f * v2 * (1.f + erff(v2 * 0.70710678118654752f));
                v3 = 0.5f * v3 * (1.f + erff(v3 * 0.70710678118654752f));
            }
            if (EPI == EPI_GELU || EPI == EPI_SPLIT) {
                __nv_bfloat16 h0, h1, h2, h3, l0, l1, l2, l3;
                split1(v0, h0, l0); split1(v1, h1, l1);
                split1(v2, h2, l2); split1(v3, h3, l3);
                *(__nv_bfloat162*)(Chi + (size_t)row * N + col) = __nv_bfloat162(h0, h1);
                *(__nv_bfloat162*)(Clo + (size_t)row * N + col) = __nv_bfloat162(l0, l1);
                *(__nv_bfloat162*)(Chi + (size_t)(row + 8) * N + col) = __nv_bfloat162(h2, h3);
                *(__nv_bfloat162*)(Clo + (size_t)(row + 8) * N + col) = __nv_bfloat162(l2, l3);
            } else if (EPI == EPI_SPLITT) {
                // transposed per-head: idx = ((b*8+h)*64 + dh)*S + s
                float vv[4] = { v0, v1, v2, v3 };
                #pragma unroll
                for (int e = 0; e < 4; e++) {
                    int rr = row + (e >> 1) * 8;
                    int ccol = col + (e & 1);
                    int b = rr >> 9, s = rr & 511;
                    int h = ccol >> 6, dh = ccol & 63;
                    size_t o = ((size_t)((b << 3) | h) * 64 + dh) * Ss + s;
                    __nv_bfloat16 hh, ll;
                    split1(vv[e], hh, ll);
                    Chi[o] = hh; Clo[o] = ll;
                }
            } else {
                *(float2*)(C + (size_t)row * N + col) = make_float2(v0, v1);
                *(float2*)(C + (size_t)(row + 8) * N + col) = make_float2(v2, v3);
            }
        }
    }
}

// ============ scores = (Q K^T)*scale — HMMA split-bf16, K=64 =================
__global__ __launch_bounds__(256, 2)
void attn_scores_mma(const __nv_bfloat16* __restrict__ qh, const __nv_bfloat16* __restrict__ ql,
                     const __nv_bfloat16* __restrict__ kh, const __nv_bfloat16* __restrict__ kl,
                     float* __restrict__ sc)
{
    extern __shared__ __align__(16) char smem[];
    const uint32_t sb = smem_u32(smem);
    const int tid = threadIdx.x;
    const int lane = tid & 31, wid = tid >> 5;
    const int wm = wid & 3, wn = wid >> 2;
    const int bh = blockIdx.z;
    const int b = bh >> 3, h = bh & 7;
    const int s1_0 = blockIdx.y * 128, s2_0 = blockIdx.x * 128;

    // one-shot load: 4 operand tiles of 128 rows x 128B
    {
        const int row = tid >> 1, half = tid & 1;
        const char* src[4];
        src[0] = (const char*)(qh + (size_t)(b * Ss + s1_0 + row) * Dd + h * DH) + half * 64;
        src[1] = (const char*)(ql + (size_t)(b * Ss + s1_0 + row) * Dd + h * DH) + half * 64;
        src[2] = (const char*)(kh + (size_t)(b * Ss + s2_0 + row) * Dd + h * DH) + half * 64;
        src[3] = (const char*)(kl + (size_t)(b * Ss + s2_0 + row) * Dd + h * DH) + half * 64;
        #pragma unroll
        for (int op = 0; op < 4; op++) {
            uint32_t d = sb + op * STILE + row * SPITCH + half * 64;
            #pragma unroll
            for (int i = 0; i < 4; i++)
                cpasync16(d + i * 16, src[op] + i * 16);
        }
        asm volatile("cp.async.commit_group;" ::: "memory");
        asm volatile("cp.async.wait_group 0;" ::: "memory");
        __syncthreads();
    }

    const uint32_t a_off = (uint32_t)((wm * 32 + (lane & 15)) * SPITCH + ((lane >> 4) & 1) * 16);
    const uint32_t b_off = (uint32_t)((wn * 64 + ((lane >> 4) << 3) + (lane & 7)) * SPITCH + ((lane >> 3) & 1) * 16);
    const uint32_t aH = sb + a_off;
    const uint32_t aL = sb + STILE + a_off;
    const uint32_t bH = sb + 2 * STILE + b_off;
    const uint32_t bL = sb + 3 * STILE + b_off;

    float acc[2][8][4];
    #pragma unroll
    for (int mf = 0; mf < 2; mf++)
        #pragma unroll
        for (int nf = 0; nf < 8; nf++)
            #pragma unroll
            for (int e = 0; e < 4; e++) acc[mf][nf][e] = 0.f;

    #pragma unroll
    for (int ks = 0; ks < 4; ks++) {
        uint32_t ah[2][4], al[2][4];
        #pragma unroll
        for (int mf = 0; mf < 2; mf++) {
            ldm4(ah[mf], aH + mf * (16 * SPITCH) + ks * 32);
            ldm4(al[mf], aL + mf * (16 * SPITCH) + ks * 32);
        }
        #pragma unroll
        for (int p = 0; p < 4; p++) {
            uint32_t bh4[4], bl4[4];
            ldm4(bh4, bH + p * (16 * SPITCH) + ks * 32);
            ldm4(bl4, bL + p * (16 * SPITCH) + ks * 32);
            #pragma unroll
            for (int mf = 0; mf < 2; mf++) {
                mma16816(acc[mf][2 * p],     ah[mf], bh4[0], bh4[1]);
                mma16816(acc[mf][2 * p + 1], ah[mf], bh4[2], bh4[3]);
                mma16816(acc[mf][2 * p],     al[mf], bh4[0], bh4[1]);
                mma16816(acc[mf][2 * p + 1], al[mf], bh4[2], bh4[3]);
                mma16816(acc[mf][2 * p],     ah[mf], bl4[0], bl4[1]);
                mma16816(acc[mf][2 * p + 1], ah[mf], bl4[2], bl4[3]);
            }
        }
    }

    const float scale = 0.125f;
    const int r0 = s1_0 + wm * 32 + (lane >> 2);
    const int cb = s2_0 + wn * 64 + (lane & 3) * 2;
    #pragma unroll
    for (int mf = 0; mf < 2; mf++) {
        #pragma unroll
        for (int nf = 0; nf < 8; nf++) {
            const int row = r0 + mf * 16;
            const int col = cb + nf * 8;
            *(float2*)(sc + ((size_t)bh * Ss + row) * Ss + col) =
                make_float2(acc[mf][nf][0] * scale, acc[mf][nf][1] * scale);
            *(float2*)(sc + ((size_t)bh * Ss + row + 8) * Ss + col) =
                make_float2(acc[mf][nf][2] * scale, acc[mf][nf][3] * scale);
        }
    }
}

// ============ softmax with mask; writes split-bf16 P =========================
__global__ __launch_bounds__(256)
void softmax_mask(const float* __restrict__ sc, const int* __restrict__ mask,
                  __nv_bfloat16* __restrict__ ph, __nv_bfloat16* __restrict__ pl)
{
    __shared__ float red[8];
    const size_t row = blockIdx.x;
    const int b = (int)(blockIdx.x / (Hh * Ss));
    const float* p = sc + row * Ss;
    const int* mr = mask + (size_t)b * Ss;
    const int tid = threadIdx.x;
    const float NEG = __int_as_float(0xff800000);

    float v0 = mr[tid] ? p[tid] : NEG;
    float v1 = mr[tid + 256] ? p[tid + 256] : NEG;

    float m = fmaxf(v0, v1);
    #pragma unroll
    for (int o = 16; o; o >>= 1) m = fmaxf(m, __shfl_xor_sync(0xffffffffu, m, o));
    if ((tid & 31) == 0) red[tid >> 5] = m;
    __syncthreads();
    m = red[0];
    #pragma unroll
    for (int i = 1; i < 8; i++) m = fmaxf(m, red[i]);
    __syncthreads();

    float e0 = __expf(v0 - m), e1 = __expf(v1 - m);
    float s = e0 + e1;
    #pragma unroll
    for (int o = 16; o; o >>= 1) s += __shfl_xor_sync(0xffffffffu, s, o);
    if ((tid & 31) == 0) red[tid >> 5] = s;
    __syncthreads();
    s = red[0] + red[1] + red[2] + red[3] + red[4] + red[5] + red[6] + red[7];

    float inv = 1.f / s;
    __nv_bfloat16 h0, l0, h1, l1;
    split1(e0 * inv, h0, l0);
    split1(e1 * inv, h1, l1);
    ph[row * Ss + tid] = h0;       pl[row * Ss + tid] = l0;
    ph[row * Ss + tid + 256] = h1; pl[row * Ss + tid + 256] = l1;
}

// ============ ctx = P @ V — HMMA split-bf16; writes split ctx ================
__global__ __launch_bounds__(256, 2)
void attn_ctx_mma(const __nv_bfloat16* __restrict__ ph, const __nv_bfloat16* __restrict__ pl,
                  const __nv_bfloat16* __restrict__ vth, const __nv_bfloat16* __restrict__ vtl,
                  __nv_bfloat16* __restrict__ ohi, __nv_bfloat16* __restrict__ olo)
{
    extern __shared__ __align__(16) char smem[];
    const uint32_t sb = smem_u32(smem);
    const int tid = threadIdx.x;
    const int lane = tid & 31, wid = tid >> 5;
    const int wm = wid & 3, wn = wid >> 2;
    const int bh = blockIdx.z;
    const int b = bh >> 3, h = bh & 7;
    const int s1_0 = blockIdx.y * 128;

    // loaders
    const int prow = tid >> 1, phalf = tid & 1;
    const char* srcPH = (const char*)(ph + ((size_t)bh * Ss + s1_0 + prow) * Ss) + phalf * 32;
    const char* srcPL = (const char*)(pl + ((size_t)bh * Ss + s1_0 + prow) * Ss) + phalf * 32;
    const int vrow = tid >> 2, vq = tid & 3;
    const char* srcVH = (const char*)(vth + ((size_t)bh * 64 + vrow) * Ss) + vq * 16;
    const char* srcVL = (const char*)(vtl + ((size_t)bh * 64 + vrow) * Ss) + vq * 16;
    const uint32_t dPH = sb + prow * CPITCH + phalf * 32;
    const uint32_t dPL = dPH + CP_TILE;
    const uint32_t dVH = sb + 2 * CP_TILE + vrow * CPITCH + vq * 16;
    const uint32_t dVL = dVH + CV_TILE;

    float acc[2][4][4];
    #pragma unroll
    for (int mf = 0; mf < 2; mf++)
        #pragma unroll
        for (int nf = 0; nf < 4; nf++)
            #pragma unroll
            for (int e = 0; e < 4; e++) acc[mf][nf][e] = 0.f;

    const uint32_t a_off = (uint32_t)((wm * 32 + (lane & 15)) * CPITCH + ((lane >> 4) & 1) * 16);
    const uint32_t b_off = (uint32_t)((wn * 32 + ((lane >> 4) << 3) + (lane & 7)) * CPITCH + ((lane >> 3) & 1) * 16);

    const int NC = Ss / 32;   // 16 chunks

    // prologue chunk 0
    cpasync16(dPH, srcPH); cpasync16(dPH + 16, srcPH + 16);
    cpasync16(dPL, srcPL); cpasync16(dPL + 16, srcPL + 16);
    cpasync16(dVH, srcVH);
    cpasync16(dVL, srcVL);
    asm volatile("cp.async.commit_group;" ::: "memory");

    for (int c = 0; c < NC; c++) {
        if (c + 1 < NC) {
            const uint32_t so = (uint32_t)(((c + 1) & 1) * CSTAGE);
            const size_t go = (size_t)(c + 1) * 64;   // 32 bf16 = 64 bytes
            cpasync16(dPH + so, srcPH + go); cpasync16(dPH + so + 16, srcPH + go + 16);
            cpasync16(dPL + so, srcPL + go); cpasync16(dPL + so + 16, srcPL + go + 16);
            cpasync16(dVH + so, srcVH + go);
            cpasync16(dVL + so, srcVL + go);
            asm volatile("cp.async.commit_group;" ::: "memory");
            asm volatile("cp.async.wait_group 1;" ::: "memory");
        } else {
            asm volatile("cp.async.wait_group 0;" ::: "memory");
        }
        __syncthreads();

        const uint32_t so = (uint32_t)((c & 1) * CSTAGE);
        const uint32_t aH = sb + so + a_off;
        const uint32_t aL = sb + so + CP_TILE + a_off;
        const uint32_t bH = sb + so + 2 * CP_TILE + b_off;
        const uint32_t bL = sb + so + 2 * CP_TILE + CV_TILE + b_off;
        #pragma unroll
        for (int ks = 0; ks < 2; ks++) {
            uint32_t ah[2][4], al[2][4];
            #pragma unroll
            for (int mf = 0; mf < 2; mf++) {
                ldm4(ah[mf], aH + mf * (16 * CPITCH) + ks * 32);
                ldm4(al[mf], aL + mf * (16 * CPITCH) + ks * 32);
            }
            #pragma unroll
            for (int p = 0; p < 2; p++) {
                uint32_t bh4[4], bl4[4];
                ldm4(bh4, bH + p * (16 * CPITCH) + ks * 32);
                ldm4(bl4, bL + p * (16 * CPITCH) + ks * 32);
                #pragma unroll
                for (int mf = 0; mf < 2; mf++) {
                    mma16816(acc[mf][2 * p],     ah[mf], bh4[0], bh4[1]);
                    mma16816(acc[mf][2 * p + 1], ah[mf], bh4[2], bh4[3]);
                    mma16816(acc[mf][2 * p],     al[mf], bh4[0], bh4[1]);
                    mma16816(acc[mf][2 * p + 1], al[mf], bh4[2], bh4[3]);
                    mma16816(acc[mf][2 * p],     ah[mf], bl4[0], bl4[1]);
                    mma16816(acc[mf][2 * p + 1], ah[mf], bl4[2], bl4[3]);
                }
            }
        }
        __syncthreads();
    }

    const int r0 = s1_0 + wm * 32 + (lane >> 2);
    const int cb = wn * 32 + (lane & 3) * 2;
    #pragma unroll
    for (int mf = 0; mf < 2; mf++) {
        #pragma unroll
        for (int nf = 0; nf < 4; nf++) {
            const int row = r0 + mf * 16;
            const int col = h * DH + cb + nf * 8;
            __nv_bfloat16 h0, h1, h2, h3, l0, l1, l2, l3;
            split1(acc[mf][nf][0], h0, l0); split1(acc[mf][nf][1], h1, l1);
            split1(acc[mf][nf][2], h2, l2); split1(acc[mf][nf][3], h3, l3);
            *(__nv_bfloat162*)(ohi + (size_t)(b * Ss + row) * Dd + col) = __nv_bfloat162(h0, h1);
            *(__nv_bfloat162*)(olo + (size_t)(b * Ss + row) * Dd + col) = __nv_bfloat162(l0, l1);
            *(__nv_bfloat162*)(ohi + (size_t)(b * Ss + row + 8) * Dd + col) = __nv_bfloat162(h2, h3);
            *(__nv_bfloat162*)(olo + (size_t)(b * Ss + row + 8) * Dd + col) = __nv_bfloat162(l2, l3);
        }
    }
}

// ============ layernorm (+ optional fused split output) ======================
__device__ __forceinline__ float block_sum_128(float v, float* red)
{
    #pragma unroll
    for (int o = 16; o; o >>= 1) v += __shfl_xor_sync(0xffffffffu, v, o);
    if ((threadIdx.x & 31) == 0) red[threadIdx.x >> 5] = v;
    __syncthreads();
    v = red[0] + red[1] + red[2] + red[3];
    __syncthreads();
    return v;
}

__device__ __forceinline__ void write_split4(__nv_bfloat16* hi, __nv_bfloat16* lo,
                                             size_t base, float4 o)
{
    __nv_bfloat16 h0, h1, h2, h3, l0, l1, l2, l3;
    split1(o.x, h0, l0); split1(o.y, h1, l1); split1(o.z, h2, l2); split1(o.w, h3, l3);
    *(__nv_bfloat162*)(hi + base) = __nv_bfloat162(h0, h1);
    *(__nv_bfloat162*)(hi + base + 2) = __nv_bfloat162(h2, h3);
    *(__nv_bfloat162*)(lo + base) = __nv_bfloat162(l0, l1);
    *(__nv_bfloat162*)(lo + base + 2) = __nv_bfloat162(l2, l3);
}

__global__ __launch_bounds__(128)
void ln_kernel(const float* __restrict__ in, float* __restrict__ out,
               const float* __restrict__ gamma, const float* __restrict__ beta,
               int vid_mode, __nv_bfloat16* __restrict__ hi, __nv_bfloat16* __restrict__ lo)
{
    __shared__ float red[4];
    const int r = blockIdx.x, tid = threadIdx.x;
    float4 v = *(const float4*)(in + (size_t)r * Dd + tid * 4);
    float s = block_sum_128(v.x + v.y + v.z + v.w, red);
    float mean = s * (1.f / Dd);
    float d0 = v.x - mean, d1 = v.y - mean, d2 = v.z - mean, d3 = v.w - mean;
    float sq = block_sum_128(d0 * d0 + d1 * d1 + d2 * d2 + d3 * d3, red);
    float inv = rsqrtf(sq * (1.f / Dd) + 1e-12f);
    int orow = vid_mode ? ((r / Tt) * Ss + Qn + (r % Tt)) : r;
    float4 gg = *(const float4*)(gamma + tid * 4);
    float4 bb = *(const float4*)(beta + tid * 4);
    float4 o;
    o.x = d0 * inv * gg.x + bb.x;
    o.y = d1 * inv * gg.y + bb.y;
    o.z = d2 * inv * gg.z + bb.z;
    o.w = d3 * inv * gg.w + bb.w;
    *(float4*)(out + (size_t)orow * Dd + tid * 4) = o;
    if (hi) write_split4(hi, lo, (size_t)orow * Dd + tid * 4, o);
}

__global__ __launch_bounds__(128)
void posmod_ln(const float* __restrict__ question, const float* __restrict__ pos,
               const float* __restrict__ mod, const float* __restrict__ gamma,
               const float* __restrict__ beta,
               __nv_bfloat16* __restrict__ hi, __nv_bfloat16* __restrict__ lo)
{
    __shared__ float red[4];
    const int r = blockIdx.x;
    const int b = r / Ss, s = r % Ss;
    const int tid = threadIdx.x;
    float4 xv;
    if (s < Qn) xv = *(const float4*)(question + ((size_t)b * Qn + s) * Dd + tid * 4);
    else        xv = *(const float4*)(g_x + (size_t)r * Dd + tid * 4);
    float4 pv = *(const float4*)(pos + (size_t)s * Dd + tid * 4);
    const float* mrow = mod + (s < Qn ? 0 : Dd);
    float4 mv = *(const float4*)(mrow + tid * 4);
    xv.x += pv.x + mv.x; xv.y += pv.y + mv.y; xv.z += pv.z + mv.z; xv.w += pv.w + mv.w;

    float su = block_sum_128(xv.x + xv.y + xv.z + xv.w, red);
    float mean = su * (1.f / Dd);
    float d0 = xv.x - mean, d1 = xv.y - mean, d2 = xv.z - mean, d3 = xv.w - mean;
    float sq = block_sum_128(d0 * d0 + d1 * d1 + d2 * d2 + d3 * d3, red);
    float inv = rsqrtf(sq * (1.f / Dd) + 1e-12f);
    float4 gg = *(const float4*)(gamma + tid * 4);
    float4 bb = *(const float4*)(beta + tid * 4);
    float4 o;
    o.x = d0 * inv * gg.x + bb.x;
    o.y = d1 * inv * gg.y + bb.y;
    o.z = d2 * inv * gg.z + bb.z;
    o.w = d3 * inv * gg.w + bb.w;
    *(float4*)(g_x + (size_t)r * Dd + tid * 4) = o;
    write_split4(hi, lo, (size_t)r * Dd + tid * 4, o);
}

// -------------------------------- launch ---------------------------------------
extern "C" void kernel_launch(void* const* d_in, const int* in_sizes, int n_in,
                              void* d_out, int out_size)
{
    const float* video    = (const float*)d_in[0];
    const float* question = (const float*)d_in[1];
    const int*   mask     = (const int*)d_in[2];
    const float* pos_emb  = (const float*)d_in[3];
    const float* mod_emb  = (const float*)d_in[4];
    const float* Wv   = (const float*)d_in[5];
    const float* bv   = (const float*)d_in[6];
    const float* nv_g = (const float*)d_in[7];
    const float* nv_b = (const float*)d_in[8];
    const float* emb_g = (const float*)d_in[9];
    const float* emb_b = (const float*)d_in[10];
    const float* Wq  = (const float*)d_in[11];
    const float* bq  = (const float*)d_in[12];
    const float* Wk  = (const float*)d_in[13];
    const float* bk  = (const float*)d_in[14];
    const float* Wva = (const float*)d_in[15];
    const float* bva = (const float*)d_in[16];
    const float* Wo  = (const float*)d_in[17];
    const float* bo  = (const float*)d_in[18];
    const float* ln1g = (const float*)d_in[19];
    const float* ln1b = (const float*)d_in[20];
    const float* W1  = (const float*)d_in[21];
    const float* b1  = (const float*)d_in[22];
    const float* W2  = (const float*)d_in[23];
    const float* b2  = (const float*)d_in[24];
    const float* ln2g = (const float*)d_in[25];
    const float* ln2b = (const float*)d_in[26];
    float* out = (float*)d_out;

    float *x, *tmp, *sc;
    __nv_bfloat16 *gah, *gal, *gbh, *gbl, *wh, *wl;
    __nv_bfloat16 *qh, *ql, *kh, *kl, *vth, *vtl, *ph, *pl;
    cudaGetSymbolAddress((void**)&x,    g_x);
    cudaGetSymbolAddress((void**)&tmp,  g_tmp);
    cudaGetSymbolAddress((void**)&sc,   g_sc);
    cudaGetSymbolAddress((void**)&gah,  ga_hi);
    cudaGetSymbolAddress((void**)&gal,  ga_lo);
    cudaGetSymbolAddress((void**)&gbh,  gb_hi);
    cudaGetSymbolAddress((void**)&gbl,  gb_lo);
    cudaGetSymbolAddress((void**)&wh,   gw_hi);
    cudaGetSymbolAddress((void**)&wl,   gw_lo);
    cudaGetSymbolAddress((void**)&qh,   g_qh);
    cudaGetSymbolAddress((void**)&ql,   g_ql);
    cudaGetSymbolAddress((void**)&kh,   g_kh);
    cudaGetSymbolAddress((void**)&kl,   g_kl);
    cudaGetSymbolAddress((void**)&vth,  g_vth);
    cudaGetSymbolAddress((void**)&vtl,  g_vtl);
    cudaGetSymbolAddress((void**)&ph,   g_ph);
    cudaGetSymbolAddress((void**)&pl,   g_pl);

    cudaFuncSetAttribute(gemm_mma<EPI_NONE>,  cudaFuncAttributeMaxDynamicSharedMemorySize, SMEM_MMA);
    cudaFuncSetAttribute(gemm_mma<EPI_RES>,   cudaFuncAttributeMaxDynamicSharedMemorySize, SMEM_MMA);
    cudaFuncSetAttribute(gemm_mma<EPI_GELU>,  cudaFuncAttributeMaxDynamicSharedMemorySize, SMEM_MMA);
    cudaFuncSetAttribute(gemm_mma<EPI_SPLIT>, cudaFuncAttributeMaxDynamicSharedMemorySize, SMEM_MMA);
    cudaFuncSetAttribute(gemm_mma<EPI_SPLITT>,cudaFuncAttributeMaxDynamicSharedMemorySize, SMEM_MMA);
    cudaFuncSetAttribute(attn_scores_mma,     cudaFuncAttributeMaxDynamicSharedMemorySize, SMEM_SC);
    cudaFuncSetAttribute(attn_ctx_mma,        cudaFuncAttributeMaxDynamicSharedMemorySize, SMEM_CTX);

    auto tsplit = [&](const float* W, int K, int N) {
        transpose_split<<<dim3(N / 32, K / 32), dim3(32, 8)>>>(W, wh, wl, K, N);
    };

    // video projection + LN into x[:, Q:, :]
    {
        size_t n4 = (size_t)BT * FDd / 4;
        split_kernel<<<(unsigned)((n4 + 255) / 256), 256>>>(video, gah, gal, n4);
    }
    tsplit(Wv, FDd, Dd);
    gemm_mma<EPI_NONE><<<dim3(Dd / 128, BT / 128), 256, SMEM_MMA>>>(gah, gal, wh, wl, bv, nullptr, tmp, nullptr, nullptr, BT, Dd, FDd);
    ln_kernel<<<BT, 128>>>(tmp, x, nv_g, nv_b, 1, nullptr, nullptr);
    posmod_ln<<<BS, 128>>>(question, pos_emb, mod_emb, emb_g, emb_b, gbh, gbl);

    for (int i = 0; i < NL; i++) {
        const size_t WO = (size_t)i * Dd * Dd;
        tsplit(Wq + WO, Dd, Dd);
        gemm_mma<EPI_SPLIT><<<dim3(Dd / 128, BS / 128), 256, SMEM_MMA>>>(gbh, gbl, wh, wl, bq + i * Dd, nullptr, nullptr, qh, ql, BS, Dd, Dd);
        tsplit(Wk + WO, Dd, Dd);
        gemm_mma<EPI_SPLIT><<<dim3(Dd / 128, BS / 128), 256, SMEM_MMA>>>(gbh, gbl, wh, wl, bk + i * Dd, nullptr, nullptr, kh, kl, BS, Dd, Dd);
        tsplit(Wva + WO, Dd, Dd);
        gemm_mma<EPI_SPLITT><<<dim3(Dd / 128, BS / 128), 256, SMEM_MMA>>>(gbh, gbl, wh, wl, bva + i * Dd, nullptr, nullptr, vth, vtl, BS, Dd, Dd);

        attn_scores_mma<<<dim3(Ss / 128, Ss / 128, Bb * Hh), 256, SMEM_SC>>>(qh, ql, kh, kl, sc);
        softmax_mask<<<Bb * Hh * Ss, 256>>>(sc, mask, ph, pl);
        attn_ctx_mma<<<dim3(1, Ss / 128, Bb * Hh), 256, SMEM_CTX>>>(ph, pl, vth, vtl, gbh, gbl);

        tsplit(Wo + WO, Dd, Dd);
        gemm_mma<EPI_RES><<<dim3(Dd / 128, BS / 128), 256, SMEM_MMA>>>(gbh, gbl, wh, wl, bo + i * Dd, x, tmp, nullptr, nullptr, BS, Dd, Dd);
        ln_kernel<<<BS, 128>>>(tmp, x, ln1g + i * Dd, ln1b + i * Dd, 0, gbh, gbl);

        tsplit(W1 + (size_t)i * Dd * FFf, Dd, FFf);
        gemm_mma<EPI_GELU><<<dim3(FFf / 128, BS / 128), 256, SMEM_MMA>>>(gbh, gbl, wh, wl, b1 + i * FFf, nullptr, nullptr, gah, gal, BS, FFf, Dd);

        tsplit(W2 + (size_t)i * FFf * Dd, FFf, Dd);
        gemm_mma<EPI_RES><<<dim3(Dd / 128, BS / 128), 256, SMEM_MMA>>>(gah, gal, wh, wl, b2 + i * Dd, x, tmp, nullptr, nullptr, BS, Dd, FFf);

        if (i == NL - 1) {
            ln_kernel<<<BS, 128>>>(tmp, out, ln2g + i * Dd, ln2b + i * Dd, 0, nullptr, nullptr);
        } else {
            ln_kernel<<<BS, 128>>>(tmp, x, ln2g + i * Dd, ln2b + i * Dd, 0, gbh, gbl);
        }
    }
}

// round 11
// speedup vs baseline: 2.5748x; 1.2564x over previous
#include <cuda_runtime.h>
#include <cuda_bf16.h>
#include <math.h>
#include <stdint.h>

#define Bb 64
#define Qn 64
#define Tt 448
#define Dd 512
#define FDd 1024
#define Hh 8
#define NL 2
#define FFf 2048
#define Ss 512
#define DH 64
#define BS (Bb*Ss)
#define BT (Bb*Tt)

// ---------------- scratch (device globals: allocation-free) ----------------
__device__ float g_x[(size_t)BS*Dd];
__device__ float g_tmp[(size_t)BS*Dd];
__device__ float g_sc[(size_t)Bb*Hh*Ss*Ss];
// split-bf16 buffers
__device__ __nv_bfloat16 ga_hi[(size_t)BS*FFf];
__device__ __nv_bfloat16 ga_lo[(size_t)BS*FFf];
__device__ __nv_bfloat16 gb_hi[(size_t)BS*Dd];
__device__ __nv_bfloat16 gb_lo[(size_t)BS*Dd];
__device__ __nv_bfloat16 gw_hi[(size_t)FFf*Dd];
__device__ __nv_bfloat16 gw_lo[(size_t)FFf*Dd];
__device__ __nv_bfloat16 g_qh[(size_t)BS*Dd];
__device__ __nv_bfloat16 g_ql[(size_t)BS*Dd];
__device__ __nv_bfloat16 g_kh[(size_t)BS*Dd];
__device__ __nv_bfloat16 g_kl[(size_t)BS*Dd];
__device__ __nv_bfloat16 g_vth[(size_t)BS*Dd];   // [B*H, 64, S]
__device__ __nv_bfloat16 g_vtl[(size_t)BS*Dd];
__device__ __nv_bfloat16 g_ph[(size_t)Bb*Hh*Ss*Ss];
__device__ __nv_bfloat16 g_pl[(size_t)Bb*Hh*Ss*Ss];

// ---------------- small helpers ----------------
__device__ __forceinline__ void split1(float v, __nv_bfloat16& h, __nv_bfloat16& l) {
    h = __float2bfloat16(v);
    l = __float2bfloat16(v - __bfloat162float(h));
}
__device__ __forceinline__ uint32_t smem_u32(const void* p) {
    uint32_t a;
    asm("{ .reg .u64 t; cvta.to.shared.u64 t, %1; cvt.u32.u64 %0, t; }" : "=r"(a) : "l"(p));
    return a;
}
__device__ __forceinline__ void ldm4(uint32_t* r, uint32_t addr) {
    asm volatile("ldmatrix.sync.aligned.m8n8.x4.shared.b16 {%0,%1,%2,%3}, [%4];"
                 : "=r"(r[0]), "=r"(r[1]), "=r"(r[2]), "=r"(r[3]) : "r"(addr));
}
__device__ __forceinline__ void mma16816(float* c, const uint32_t* a, uint32_t b0, uint32_t b1) {
    asm volatile("mma.sync.aligned.m16n8k16.row.col.f32.bf16.bf16.f32 "
                 "{%0,%1,%2,%3}, {%4,%5,%6,%7}, {%8,%9}, {%0,%1,%2,%3};"
                 : "+f"(c[0]), "+f"(c[1]), "+f"(c[2]), "+f"(c[3])
                 : "r"(a[0]), "r"(a[1]), "r"(a[2]), "r"(a[3]), "r"(b0), "r"(b1));
}
__device__ __forceinline__ void cpasync16(uint32_t dst, const void* src) {
    asm volatile("cp.async.cg.shared.global [%0], [%1], 16;" :: "r"(dst), "l"(src));
}

// gemm smem geometry: 4-stage, K=16 chunk, pitch 48
#define GP      48
#define OP_TILE (128 * GP)          // 6144
#define STG     (4 * OP_TILE)       // 24576 per stage (4 operands)
#define SMEM_MMA (4 * STG)          // 98304
// scores smem geometry
#define SPITCH 144
#define STILE  (128 * SPITCH)
#define SMEM_SC (4 * STILE)
// ctx smem geometry
#define CPITCH 80
#define CP_TILE (128 * CPITCH)
#define CV_TILE (64 * CPITCH)
#define CSTAGE (2 * CP_TILE + 2 * CV_TILE)
#define SMEM_CTX (2 * CSTAGE)

// ============ split conversion (video input only) ============
__global__ __launch_bounds__(256)
void split_kernel(const float* __restrict__ in, __nv_bfloat16* __restrict__ hi,
                  __nv_bfloat16* __restrict__ lo, size_t n4)
{
    size_t i = (size_t)blockIdx.x * 256 + threadIdx.x;
    if (i >= n4) return;
    float4 v = ((const float4*)in)[i];
    __nv_bfloat16 h0, h1, h2, h3, l0, l1, l2, l3;
    split1(v.x, h0, l0); split1(v.y, h1, l1); split1(v.z, h2, l2); split1(v.w, h3, l3);
    ((__nv_bfloat162*)hi)[2 * i] = __nv_bfloat162(h0, h1);
    ((__nv_bfloat162*)hi)[2 * i + 1] = __nv_bfloat162(h2, h3);
    ((__nv_bfloat162*)lo)[2 * i] = __nv_bfloat162(l0, l1);
    ((__nv_bfloat162*)lo)[2 * i + 1] = __nv_bfloat162(l2, l3);
}

// W[K][N] fp32 -> out[N][K] split bf16
__global__ __launch_bounds__(256)
void transpose_split(const float* __restrict__ W, __nv_bfloat16* __restrict__ hi,
                     __nv_bfloat16* __restrict__ lo, int K, int N)
{
    __shared__ float t[32][33];
    const int n0 = blockIdx.x * 32, k0 = blockIdx.y * 32;
    const int tx = threadIdx.x, ty = threadIdx.y;
    #pragma unroll
    for (int j = 0; j < 4; j++)
        t[ty + j * 8][tx] = W[(size_t)(k0 + ty + j * 8) * N + n0 + tx];
    __syncthreads();
    #pragma unroll
    for (int j = 0; j < 4; j++) {
        int n = n0 + ty + j * 8, kk = k0 + tx;
        __nv_bfloat16 h, l;
        split1(t[tx][ty + j * 8], h, l);
        hi[(size_t)n * K + kk] = h;
        lo[(size_t)n * K + kk] = l;
    }
}

// ============ HMMA split-bf16 GEMM — 4-stage pipeline ==============
// 0: fp32 C    1: fp32 C + res    2: gelu -> split bf16
// 3: split bf16 (normal layout)   4: split bf16 transposed per-head [B*H,64,S]
enum { EPI_NONE = 0, EPI_RES = 1, EPI_GELU = 2, EPI_SPLIT = 3, EPI_SPLITT = 4 };

template<int EPI>
__global__ __launch_bounds__(256, 2)
void gemm_mma(const __nv_bfloat16* __restrict__ a_hi, const __nv_bfloat16* __restrict__ a_lo,
              const __nv_bfloat16* __restrict__ w_hi, const __nv_bfloat16* __restrict__ w_lo,
              const float* __restrict__ bias, const float* __restrict__ res,
              float* __restrict__ C, __nv_bfloat16* __restrict__ Chi,
              __nv_bfloat16* __restrict__ Clo, int M, int N, int K)
{
    extern __shared__ __align__(16) char smem[];
    const uint32_t sb = smem_u32(smem);
    const int tid = threadIdx.x;
    const int lane = tid & 31, wid = tid >> 5;
    const int wm = wid & 3, wn = wid >> 2;
    const int bm = blockIdx.y * 128, bn = blockIdx.x * 128;

    // ---- cp.async geometry: per chunk (K=16): thread -> (row, 16B half) per op ----
    const int crow = tid >> 1;
    const int chalf = (tid & 1) * 16;
    const char* gsrc[4];
    gsrc[0] = (const char*)a_hi + (size_t)(bm + crow) * K * 2 + chalf;
    gsrc[1] = (const char*)a_lo + (size_t)(bm + crow) * K * 2 + chalf;
    gsrc[2] = (const char*)w_hi + (size_t)(bn + crow) * K * 2 + chalf;
    gsrc[3] = (const char*)w_lo + (size_t)(bn + crow) * K * 2 + chalf;
    uint32_t sdst[4];
    #pragma unroll
    for (int op = 0; op < 4; op++)
        sdst[op] = sb + op * OP_TILE + crow * GP + chalf;

    // ---- ldmatrix per-thread base addresses ----
    const uint32_t a_off = (uint32_t)((wm * 32 + (lane & 15)) * GP + ((lane >> 4) & 1) * 16);
    const uint32_t b_off = (uint32_t)((wn * 64 + ((lane >> 4) << 3) + (lane & 7)) * GP + ((lane >> 3) & 1) * 16);

    float acc[2][8][4];
    #pragma unroll
    for (int mf = 0; mf < 2; mf++)
        #pragma unroll
        for (int nf = 0; nf < 8; nf++)
            #pragma unroll
            for (int e = 0; e < 4; e++) acc[mf][nf][e] = 0.f;

    const int NC = K >> 4;

    // prologue: issue chunks 0,1,2 into stages 0,1,2
    #pragma unroll
    for (int s = 0; s < 3; s++) {
        const uint32_t so = (uint32_t)(s * STG);
        const size_t go = (size_t)s * 32;
        #pragma unroll
        for (int op = 0; op < 4; op++)
            cpasync16(sdst[op] + so, gsrc[op] + go);
        asm volatile("cp.async.commit_group;" ::: "memory");
    }

    for (int c = 0; c < NC; c++) {
        asm volatile("cp.async.wait_group 2;" ::: "memory");
        __syncthreads();
        if (c + 3 < NC) {
            const uint32_t so = (uint32_t)(((c + 3) & 3) * STG);
            const size_t go = (size_t)(c + 3) * 32;
            #pragma unroll
            for (int op = 0; op < 4; op++)
                cpasync16(sdst[op] + so, gsrc[op] + go);
        }
        asm volatile("cp.async.commit_group;" ::: "memory");

        const uint32_t so = (uint32_t)((c & 3) * STG);
        const uint32_t aH = sb + so + a_off;
        const uint32_t aL = sb + so + OP_TILE + a_off;
        const uint32_t bHb = sb + so + 2 * OP_TILE + b_off;
        const uint32_t bLb = sb + so + 3 * OP_TILE + b_off;

        uint32_t ah[2][4], al[2][4];
        #pragma unroll
        for (int mf = 0; mf < 2; mf++) {
            ldm4(ah[mf], aH + mf * (16 * GP));
            ldm4(al[mf], aL + mf * (16 * GP));
        }
        #pragma unroll
        for (int p = 0; p < 4; p++) {
            uint32_t bh[4], bl[4];
            ldm4(bh, bHb + p * (16 * GP));
            ldm4(bl, bLb + p * (16 * GP));
            #pragma unroll
            for (int mf = 0; mf < 2; mf++) {
                mma16816(acc[mf][2 * p],     ah[mf], bh[0], bh[1]);
                mma16816(acc[mf][2 * p + 1], ah[mf], bh[2], bh[3]);
                mma16816(acc[mf][2 * p],     al[mf], bh[0], bh[1]);
                mma16816(acc[mf][2 * p + 1], al[mf], bh[2], bh[3]);
                mma16816(acc[mf][2 * p],     ah[mf], bl[0], bl[1]);
                mma16816(acc[mf][2 * p + 1], ah[mf], bl[2], bl[3]);
            }
        }
    }

    // ---- epilogue ----
    const int r0 = bm + wm * 32 + (lane >> 2);
    const int cb = bn + wn * 64 + (lane & 3) * 2;
    #pragma unroll
    for (int mf = 0; mf < 2; mf++) {
        #pragma unroll
        for (int nf = 0; nf < 8; nf++) {
            const int row = r0 + mf * 16;
            const int col = cb + nf * 8;
            float2 bv = *(const float2*)(bias + col);
            float v0 = acc[mf][nf][0] + bv.x, v1 = acc[mf][nf][1] + bv.y;
            float v2 = acc[mf][nf][2] + bv.x, v3 = acc[mf][nf][3] + bv.y;
            if (EPI == EPI_RES) {
                float2 ra = *(const float2*)(res + (size_t)row * N + col);
                float2 rb = *(const float2*)(res + (size_t)(row + 8) * N + col);
                v0 += ra.x; v1 += ra.y; v2 += rb.x; v3 += rb.y;
            }
            if (EPI == EPI_GELU) {
                v0 = 0.5f * v0 * (1.f + erff(v0 * 0.70710678118654752f));
                v1 = 0.5f * v1 * (1.f + erff(v1 * 0.70710678118654752f));
                v2 = 0.5f * v2 * (1.f + erff(v2 * 0.70710678118654752f));
                v3 = 0.5f * v3 * (1.f + erff(v3 * 0.70710678118654752f));
            }
            if (EPI == EPI_GELU || EPI == EPI_SPLIT) {
                __nv_bfloat16 h0, h1, h2, h3, l0, l1, l2, l3;
                split1(v0, h0, l0); split1(v1, h1, l1);
                split1(v2, h2, l2); split1(v3, h3, l3);
                *(__nv_bfloat162*)(Chi + (size_t)row * N + col) = __nv_bfloat162(h0, h1);
                *(__nv_bfloat162*)(Clo + (size_t)row * N + col) = __nv_bfloat162(l0, l1);
                *(__nv_bfloat162*)(Chi + (size_t)(row + 8) * N + col) = __nv_bfloat162(h2, h3);
                *(__nv_bfloat162*)(Clo + (size_t)(row + 8) * N + col) = __nv_bfloat162(l2, l3);
            } else if (EPI == EPI_SPLITT) {
                // transposed per-head: idx = ((b*8+h)*64 + dh)*S + s
                float vv[4] = { v0, v1, v2, v3 };
                #pragma unroll
                for (int e = 0; e < 4; e++) {
                    int rr = row + (e >> 1) * 8;
                    int ccol = col + (e & 1);
                    int b = rr >> 9, s = rr & 511;
                    int h = ccol >> 6, dh = ccol & 63;
                    size_t o = ((size_t)((b << 3) | h) * 64 + dh) * Ss + s;
                    __nv_bfloat16 hh, ll;
                    split1(vv[e], hh, ll);
                    Chi[o] = hh; Clo[o] = ll;
                }
            } else {
                *(float2*)(C + (size_t)row * N + col) = make_float2(v0, v1);
                *(float2*)(C + (size_t)(row + 8) * N + col) = make_float2(v2, v3);
            }
        }
    }
}

// ============ scores = (Q K^T)*scale — HMMA split-bf16, K=64 =================
__global__ __launch_bounds__(256, 2)
void attn_scores_mma(const __nv_bfloat16* __restrict__ qh, const __nv_bfloat16* __restrict__ ql,
                     const __nv_bfloat16* __restrict__ kh, const __nv_bfloat16* __restrict__ kl,
                     float* __restrict__ sc)
{
    extern __shared__ __align__(16) char smem[];
    const uint32_t sb = smem_u32(smem);
    const int tid = threadIdx.x;
    const int lane = tid & 31, wid = tid >> 5;
    const int wm = wid & 3, wn = wid >> 2;
    const int bh = blockIdx.z;
    const int b = bh >> 3, h = bh & 7;
    const int s1_0 = blockIdx.y * 128, s2_0 = blockIdx.x * 128;

    {
        const int row = tid >> 1, half = tid & 1;
        const char* src[4];
        src[0] = (const char*)(qh + (size_t)(b * Ss + s1_0 + row) * Dd + h * DH) + half * 64;
        src[1] = (const char*)(ql + (size_t)(b * Ss + s1_0 + row) * Dd + h * DH) + half * 64;
        src[2] = (const char*)(kh + (size_t)(b * Ss + s2_0 + row) * Dd + h * DH) + half * 64;
        src[3] = (const char*)(kl + (size_t)(b * Ss + s2_0 + row) * Dd + h * DH) + half * 64;
        #pragma unroll
        for (int op = 0; op < 4; op++) {
            uint32_t d = sb + op * STILE + row * SPITCH + half * 64;
            #pragma unroll
            for (int i = 0; i < 4; i++)
                cpasync16(d + i * 16, src[op] + i * 16);
        }
        asm volatile("cp.async.commit_group;" ::: "memory");
        asm volatile("cp.async.wait_group 0;" ::: "memory");
        __syncthreads();
    }

    const uint32_t a_off = (uint32_t)((wm * 32 + (lane & 15)) * SPITCH + ((lane >> 4) & 1) * 16);
    const uint32_t b_off = (uint32_t)((wn * 64 + ((lane >> 4) << 3) + (lane & 7)) * SPITCH + ((lane >> 3) & 1) * 16);
    const uint32_t aH = sb + a_off;
    const uint32_t aL = sb + STILE + a_off;
    const uint32_t bH = sb + 2 * STILE + b_off;
    const uint32_t bL = sb + 3 * STILE + b_off;

    float acc[2][8][4];
    #pragma unroll
    for (int mf = 0; mf < 2; mf++)
        #pragma unroll
        for (int nf = 0; nf < 8; nf++)
            #pragma unroll
            for (int e = 0; e < 4; e++) acc[mf][nf][e] = 0.f;

    #pragma unroll
    for (int ks = 0; ks < 4; ks++) {
        uint32_t ah[2][4], al[2][4];
        #pragma unroll
        for (int mf = 0; mf < 2; mf++) {
            ldm4(ah[mf], aH + mf * (16 * SPITCH) + ks * 32);
            ldm4(al[mf], aL + mf * (16 * SPITCH) + ks * 32);
        }
        #pragma unroll
        for (int p = 0; p < 4; p++) {
            uint32_t bh4[4], bl4[4];
            ldm4(bh4, bH + p * (16 * SPITCH) + ks * 32);
            ldm4(bl4, bL + p * (16 * SPITCH) + ks * 32);
            #pragma unroll
            for (int mf = 0; mf < 2; mf++) {
                mma16816(acc[mf][2 * p],     ah[mf], bh4[0], bh4[1]);
                mma16816(acc[mf][2 * p + 1], ah[mf], bh4[2], bh4[3]);
                mma16816(acc[mf][2 * p],     al[mf], bh4[0], bh4[1]);
                mma16816(acc[mf][2 * p + 1], al[mf], bh4[2], bh4[3]);
                mma16816(acc[mf][2 * p],     ah[mf], bl4[0], bl4[1]);
                mma16816(acc[mf][2 * p + 1], ah[mf], bl4[2], bl4[3]);
            }
        }
    }

    const float scale = 0.125f;
    const int r0 = s1_0 + wm * 32 + (lane >> 2);
    const int cb = s2_0 + wn * 64 + (lane & 3) * 2;
    #pragma unroll
    for (int mf = 0; mf < 2; mf++) {
        #pragma unroll
        for (int nf = 0; nf < 8; nf++) {
            const int row = r0 + mf * 16;
            const int col = cb + nf * 8;
            *(float2*)(sc + ((size_t)bh * Ss + row) * Ss + col) =
                make_float2(acc[mf][nf][0] * scale, acc[mf][nf][1] * scale);
            *(float2*)(sc + ((size_t)bh * Ss + row + 8) * Ss + col) =
                make_float2(acc[mf][nf][2] * scale, acc[mf][nf][3] * scale);
        }
    }
}

// ============ softmax with mask; writes split-bf16 P =========================
__global__ __launch_bounds__(256)
void softmax_mask(const float* __restrict__ sc, const int* __restrict__ mask,
                  __nv_bfloat16* __restrict__ ph, __nv_bfloat16* __restrict__ pl)
{
    __shared__ float red[8];
    const size_t row = blockIdx.x;
    const int b = (int)(blockIdx.x / (Hh * Ss));
    const float* p = sc + row * Ss;
    const int* mr = mask + (size_t)b * Ss;
    const int tid = threadIdx.x;
    const float NEG = __int_as_float(0xff800000);

    float v0 = mr[tid] ? p[tid] : NEG;
    float v1 = mr[tid + 256] ? p[tid + 256] : NEG;

    float m = fmaxf(v0, v1);
    #pragma unroll
    for (int o = 16; o; o >>= 1) m = fmaxf(m, __shfl_xor_sync(0xffffffffu, m, o));
    if ((tid & 31) == 0) red[tid >> 5] = m;
    __syncthreads();
    m = red[0];
    #pragma unroll
    for (int i = 1; i < 8; i++) m = fmaxf(m, red[i]);
    __syncthreads();

    float e0 = __expf(v0 - m), e1 = __expf(v1 - m);
    float s = e0 + e1;
    #pragma unroll
    for (int o = 16; o; o >>= 1) s += __shfl_xor_sync(0xffffffffu, s, o);
    if ((tid & 31) == 0) red[tid >> 5] = s;
    __syncthreads();
    s = red[0] + red[1] + red[2] + red[3] + red[4] + red[5] + red[6] + red[7];

    float inv = 1.f / s;
    __nv_bfloat16 h0, l0, h1, l1;
    split1(e0 * inv, h0, l0);
    split1(e1 * inv, h1, l1);
    ph[row * Ss + tid] = h0;       pl[row * Ss + tid] = l0;
    ph[row * Ss + tid + 256] = h1; pl[row * Ss + tid + 256] = l1;
}

// ============ ctx = P @ V — HMMA split-bf16; writes split ctx ================
__global__ __launch_bounds__(256, 2)
void attn_ctx_mma(const __nv_bfloat16* __restrict__ ph, const __nv_bfloat16* __restrict__ pl,
                  const __nv_bfloat16* __restrict__ vth, const __nv_bfloat16* __restrict__ vtl,
                  __nv_bfloat16* __restrict__ ohi, __nv_bfloat16* __restrict__ olo)
{
    extern __shared__ __align__(16) char smem[];
    const uint32_t sb = smem_u32(smem);
    const int tid = threadIdx.x;
    const int lane = tid & 31, wid = tid >> 5;
    const int wm = wid & 3, wn = wid >> 2;
    const int bh = blockIdx.z;
    const int b = bh >> 3, h = bh & 7;
    const int s1_0 = blockIdx.y * 128;

    const int prow = tid >> 1, phalf = tid & 1;
    const char* srcPH = (const char*)(ph + ((size_t)bh * Ss + s1_0 + prow) * Ss) + phalf * 32;
    const char* srcPL = (const char*)(pl + ((size_t)bh * Ss + s1_0 + prow) * Ss) + phalf * 32;
    const int vrow = tid >> 2, vq = tid & 3;
    const char* srcVH = (const char*)(vth + ((size_t)bh * 64 + vrow) * Ss) + vq * 16;
    const char* srcVL = (const char*)(vtl + ((size_t)bh * 64 + vrow) * Ss) + vq * 16;
    const uint32_t dPH = sb + prow * CPITCH + phalf * 32;
    const uint32_t dPL = dPH + CP_TILE;
    const uint32_t dVH = sb + 2 * CP_TILE + vrow * CPITCH + vq * 16;
    const uint32_t dVL = dVH + CV_TILE;

    float acc[2][4][4];
    #pragma unroll
    for (int mf = 0; mf < 2; mf++)
        #pragma unroll
        for (int nf = 0; nf < 4; nf++)
            #pragma unroll
            for (int e = 0; e < 4; e++) acc[mf][nf][e] = 0.f;

    const uint32_t a_off = (uint32_t)((wm * 32 + (lane & 15)) * CPITCH + ((lane >> 4) & 1) * 16);
    const uint32_t b_off = (uint32_t)((wn * 32 + ((lane >> 4) << 3) + (lane & 7)) * CPITCH + ((lane >> 3) & 1) * 16);

    const int NC = Ss / 32;

    cpasync16(dPH, srcPH); cpasync16(dPH + 16, srcPH + 16);
    cpasync16(dPL, srcPL); cpasync16(dPL + 16, srcPL + 16);
    cpasync16(dVH, srcVH);
    cpasync16(dVL, srcVL);
    asm volatile("cp.async.commit_group;" ::: "memory");

    for (int c = 0; c < NC; c++) {
        if (c + 1 < NC) {
            const uint32_t so = (uint32_t)(((c + 1) & 1) * CSTAGE);
            const size_t go = (size_t)(c + 1) * 64;
            cpasync16(dPH + so, srcPH + go); cpasync16(dPH + so + 16, srcPH + go + 16);
            cpasync16(dPL + so, srcPL + go); cpasync16(dPL + so + 16, srcPL + go + 16);
            cpasync16(dVH + so, srcVH + go);
            cpasync16(dVL + so, srcVL + go);
            asm volatile("cp.async.commit_group;" ::: "memory");
            asm volatile("cp.async.wait_group 1;" ::: "memory");
        } else {
            asm volatile("cp.async.wait_group 0;" ::: "memory");
        }
        __syncthreads();

        const uint32_t so = (uint32_t)((c & 1) * CSTAGE);
        const uint32_t aH = sb + so + a_off;
        const uint32_t aL = sb + so + CP_TILE + a_off;
        const uint32_t bH = sb + so + 2 * CP_TILE + b_off;
        const uint32_t bL = sb + so + 2 * CP_TILE + CV_TILE + b_off;
        #pragma unroll
        for (int ks = 0; ks < 2; ks++) {
            uint32_t ah[2][4], al[2][4];
            #pragma unroll
            for (int mf = 0; mf < 2; mf++) {
                ldm4(ah[mf], aH + mf * (16 * CPITCH) + ks * 32);
                ldm4(al[mf], aL + mf * (16 * CPITCH) + ks * 32);
            }
            #pragma unroll
            for (int p = 0; p < 2; p++) {
                uint32_t bh4[4], bl4[4];
                ldm4(bh4, bH + p * (16 * CPITCH) + ks * 32);
                ldm4(bl4, bL + p * (16 * CPITCH) + ks * 32);
                #pragma unroll
                for (int mf = 0; mf < 2; mf++) {
                    mma16816(acc[mf][2 * p],     ah[mf], bh4[0], bh4[1]);
                    mma16816(acc[mf][2 * p + 1], ah[mf], bh4[2], bh4[3]);
                    mma16816(acc[mf][2 * p],     al[mf], bh4[0], bh4[1]);
                    mma16816(acc[mf][2 * p + 1], al[mf], bh4[2], bh4[3]);
                    mma16816(acc[mf][2 * p],     ah[mf], bl4[0], bl4[1]);
                    mma16816(acc[mf][2 * p + 1], ah[mf], bl4[2], bl4[3]);
                }
            }
        }
        __syncthreads();
    }

    const int r0 = s1_0 + wm * 32 + (lane >> 2);
    const int cb = wn * 32 + (lane & 3) * 2;
    #pragma unroll
    for (int mf = 0; mf < 2; mf++) {
        #pragma unroll
        for (int nf = 0; nf < 4; nf++) {
            const int row = r0 + mf * 16;
            const int col = h * DH + cb + nf * 8;
            __nv_bfloat16 h0, h1, h2, h3, l0, l1, l2, l3;
            split1(acc[mf][nf][0], h0, l0); split1(acc[mf][nf][1], h1, l1);
            split1(acc[mf][nf][2], h2, l2); split1(acc[mf][nf][3], h3, l3);
            *(__nv_bfloat162*)(ohi + (size_t)(b * Ss + row) * Dd + col) = __nv_bfloat162(h0, h1);
            *(__nv_bfloat162*)(olo + (size_t)(b * Ss + row) * Dd + col) = __nv_bfloat162(l0, l1);
            *(__nv_bfloat162*)(ohi + (size_t)(b * Ss + row + 8) * Dd + col) = __nv_bfloat162(h2, h3);
            *(__nv_bfloat162*)(olo + (size_t)(b * Ss + row + 8) * Dd + col) = __nv_bfloat162(l2, l3);
        }
    }
}

// ============ layernorm (+ optional fused split output) ======================
__device__ __forceinline__ float block_sum_128(float v, float* red)
{
    #pragma unroll
    for (int o = 16; o; o >>= 1) v += __shfl_xor_sync(0xffffffffu, v, o);
    if ((threadIdx.x & 31) == 0) red[threadIdx.x >> 5] = v;
    __syncthreads();
    v = red[0] + red[1] + red[2] + red[3];
    __syncthreads();
    return v;
}

__device__ __forceinline__ void write_split4(__nv_bfloat16* hi, __nv_bfloat16* lo,
                                             size_t base, float4 o)
{
    __nv_bfloat16 h0, h1, h2, h3, l0, l1, l2, l3;
    split1(o.x, h0, l0); split1(o.y, h1, l1); split1(o.z, h2, l2); split1(o.w, h3, l3);
    *(__nv_bfloat162*)(hi + base) = __nv_bfloat162(h0, h1);
    *(__nv_bfloat162*)(hi + base + 2) = __nv_bfloat162(h2, h3);
    *(__nv_bfloat162*)(lo + base) = __nv_bfloat162(l0, l1);
    *(__nv_bfloat162*)(lo + base + 2) = __nv_bfloat162(l2, l3);
}

__global__ __launch_bounds__(128)
void ln_kernel(const float* __restrict__ in, float* __restrict__ out,
               const float* __restrict__ gamma, const float* __restrict__ beta,
               int vid_mode, __nv_bfloat16* __restrict__ hi, __nv_bfloat16* __restrict__ lo)
{
    __shared__ float red[4];
    const int r = blockIdx.x, tid = threadIdx.x;
    float4 v = *(const float4*)(in + (size_t)r * Dd + tid * 4);
    float s = block_sum_128(v.x + v.y + v.z + v.w, red);
    float mean = s * (1.f / Dd);
    float d0 = v.x - mean, d1 = v.y - mean, d2 = v.z - mean, d3 = v.w - mean;
    float sq = block_sum_128(d0 * d0 + d1 * d1 + d2 * d2 + d3 * d3, red);
    float inv = rsqrtf(sq * (1.f / Dd) + 1e-12f);
    int orow = vid_mode ? ((r / Tt) * Ss + Qn + (r % Tt)) : r;
    float4 gg = *(const float4*)(gamma + tid * 4);
    float4 bb = *(const float4*)(beta + tid * 4);
    float4 o;
    o.x = d0 * inv * gg.x + bb.x;
    o.y = d1 * inv * gg.y + bb.y;
    o.z = d2 * inv * gg.z + bb.z;
    o.w = d3 * inv * gg.w + bb.w;
    *(float4*)(out + (size_t)orow * Dd + tid * 4) = o;
    if (hi) write_split4(hi, lo, (size_t)orow * Dd + tid * 4, o);
}

__global__ __launch_bounds__(128)
void posmod_ln(const float* __restrict__ question, const float* __restrict__ pos,
               const float* __restrict__ mod, const float* __restrict__ gamma,
               const float* __restrict__ beta,
               __nv_bfloat16* __restrict__ hi, __nv_bfloat16* __restrict__ lo)
{
    __shared__ float red[4];
    const int r = blockIdx.x;
    const int b = r / Ss, s = r % Ss;
    const int tid = threadIdx.x;
    float4 xv;
    if (s < Qn) xv = *(const float4*)(question + ((size_t)b * Qn + s) * Dd + tid * 4);
    else        xv = *(const float4*)(g_x + (size_t)r * Dd + tid * 4);
    float4 pv = *(const float4*)(pos + (size_t)s * Dd + tid * 4);
    const float* mrow = mod + (s < Qn ? 0 : Dd);
    float4 mv = *(const float4*)(mrow + tid * 4);
    xv.x += pv.x + mv.x; xv.y += pv.y + mv.y; xv.z += pv.z + mv.z; xv.w += pv.w + mv.w;

    float su = block_sum_128(xv.x + xv.y + xv.z + xv.w, red);
    float mean = su * (1.f / Dd);
    float d0 = xv.x - mean, d1 = xv.y - mean, d2 = xv.z - mean, d3 = xv.w - mean;
    float sq = block_sum_128(d0 * d0 + d1 * d1 + d2 * d2 + d3 * d3, red);
    float inv = rsqrtf(sq * (1.f / Dd) + 1e-12f);
    float4 gg = *(const float4*)(gamma + tid * 4);
    float4 bb = *(const float4*)(beta + tid * 4);
    float4 o;
    o.x = d0 * inv * gg.x + bb.x;
    o.y = d1 * inv * gg.y + bb.y;
    o.z = d2 * inv * gg.z + bb.z;
    o.w = d3 * inv * gg.w + bb.w;
    *(float4*)(g_x + (size_t)r * Dd + tid * 4) = o;
    write_split4(hi, lo, (size_t)r * Dd + tid * 4, o);
}

// -------------------------------- launch ---------------------------------------
extern "C" void kernel_launch(void* const* d_in, const int* in_sizes, int n_in,
                              void* d_out, int out_size)
{
    const float* video    = (const float*)d_in[0];
    const float* question = (const float*)d_in[1];
    const int*   mask     = (const int*)d_in[2];
    const float* pos_emb  = (const float*)d_in[3];
    const float* mod_emb  = (const float*)d_in[4];
    const float* Wv   = (const float*)d_in[5];
    const float* bv   = (const float*)d_in[6];
    const float* nv_g = (const float*)d_in[7];
    const float* nv_b = (const float*)d_in[8];
    const float* emb_g = (const float*)d_in[9];
    const float* emb_b = (const float*)d_in[10];
    const float* Wq  = (const float*)d_in[11];
    const float* bq  = (const float*)d_in[12];
    const float* Wk  = (const float*)d_in[13];
    const float* bk  = (const float*)d_in[14];
    const float* Wva = (const float*)d_in[15];
    const float* bva = (const float*)d_in[16];
    const float* Wo  = (const float*)d_in[17];
    const float* bo  = (const float*)d_in[18];
    const float* ln1g = (const float*)d_in[19];
    const float* ln1b = (const float*)d_in[20];
    const float* W1  = (const float*)d_in[21];
    const float* b1  = (const float*)d_in[22];
    const float* W2  = (const float*)d_in[23];
    const float* b2  = (const float*)d_in[24];
    const float* ln2g = (const float*)d_in[25];
    const float* ln2b = (const float*)d_in[26];
    float* out = (float*)d_out;

    float *x, *tmp, *sc;
    __nv_bfloat16 *gah, *gal, *gbh, *gbl, *wh, *wl;
    __nv_bfloat16 *qh, *ql, *kh, *kl, *vth, *vtl, *ph, *pl;
    cudaGetSymbolAddress((void**)&x,    g_x);
    cudaGetSymbolAddress((void**)&tmp,  g_tmp);
    cudaGetSymbolAddress((void**)&sc,   g_sc);
    cudaGetSymbolAddress((void**)&gah,  ga_hi);
    cudaGetSymbolAddress((void**)&gal,  ga_lo);
    cudaGetSymbolAddress((void**)&gbh,  gb_hi);
    cudaGetSymbolAddress((void**)&gbl,  gb_lo);
    cudaGetSymbolAddress((void**)&wh,   gw_hi);
    cudaGetSymbolAddress((void**)&wl,   gw_lo);
    cudaGetSymbolAddress((void**)&qh,   g_qh);
    cudaGetSymbolAddress((void**)&ql,   g_ql);
    cudaGetSymbolAddress((void**)&kh,   g_kh);
    cudaGetSymbolAddress((void**)&kl,   g_kl);
    cudaGetSymbolAddress((void**)&vth,  g_vth);
    cudaGetSymbolAddress((void**)&vtl,  g_vtl);
    cudaGetSymbolAddress((void**)&ph,   g_ph);
    cudaGetSymbolAddress((void**)&pl,   g_pl);

    cudaFuncSetAttribute(gemm_mma<EPI_NONE>,  cudaFuncAttributeMaxDynamicSharedMemorySize, SMEM_MMA);
    cudaFuncSetAttribute(gemm_mma<EPI_RES>,   cudaFuncAttributeMaxDynamicSharedMemorySize, SMEM_MMA);
    cudaFuncSetAttribute(gemm_mma<EPI_GELU>,  cudaFuncAttributeMaxDynamicSharedMemorySize, SMEM_MMA);
    cudaFuncSetAttribute(gemm_mma<EPI_SPLIT>, cudaFuncAttributeMaxDynamicSharedMemorySize, SMEM_MMA);
    cudaFuncSetAttribute(gemm_mma<EPI_SPLITT>,cudaFuncAttributeMaxDynamicSharedMemorySize, SMEM_MMA);
    cudaFuncSetAttribute(attn_scores_mma,     cudaFuncAttributeMaxDynamicSharedMemorySize, SMEM_SC);
    cudaFuncSetAttribute(attn_ctx_mma,        cudaFuncAttributeMaxDynamicSharedMemorySize, SMEM_CTX);

    auto tsplit = [&](const float* W, int K, int N) {
        transpose_split<<<dim3(N / 32, K / 32), dim3(32, 8)>>>(W, wh, wl, K, N);
    };

    // video projection + LN into x[:, Q:, :]
    {
        size_t n4 = (size_t)BT * FDd / 4;
        split_kernel<<<(unsigned)((n4 + 255) / 256), 256>>>(video, gah, gal, n4);
    }
    tsplit(Wv, FDd, Dd);
    gemm_mma<EPI_NONE><<<dim3(Dd / 128, BT / 128), 256, SMEM_MMA>>>(gah, gal, wh, wl, bv, nullptr, tmp, nullptr, nullptr, BT, Dd, FDd);
    ln_kernel<<<BT, 128>>>(tmp, x, nv_g, nv_b, 1, nullptr, nullptr);
    posmod_ln<<<BS, 128>>>(question, pos_emb, mod_emb, emb_g, emb_b, gbh, gbl);

    for (int i = 0; i < NL; i++) {
        const size_t WO = (size_t)i * Dd * Dd;
        tsplit(Wq + WO, Dd, Dd);
        gemm_mma<EPI_SPLIT><<<dim3(Dd / 128, BS / 128), 256, SMEM_MMA>>>(gbh, gbl, wh, wl, bq + i * Dd, nullptr, nullptr, qh, ql, BS, Dd, Dd);
        tsplit(Wk + WO, Dd, Dd);
        gemm_mma<EPI_SPLIT><<<dim3(Dd / 128, BS / 128), 256, SMEM_MMA>>>(gbh, gbl, wh, wl, bk + i * Dd, nullptr, nullptr, kh, kl, BS, Dd, Dd);
        tsplit(Wva + WO, Dd, Dd);
        gemm_mma<EPI_SPLITT><<<dim3(Dd / 128, BS / 128), 256, SMEM_MMA>>>(gbh, gbl, wh, wl, bva + i * Dd, nullptr, nullptr, vth, vtl, BS, Dd, Dd);

        attn_scores_mma<<<dim3(Ss / 128, Ss / 128, Bb * Hh), 256, SMEM_SC>>>(qh, ql, kh, kl, sc);
        softmax_mask<<<Bb * Hh * Ss, 256>>>(sc, mask, ph, pl);
        attn_ctx_mma<<<dim3(1, Ss / 128, Bb * Hh), 256, SMEM_CTX>>>(ph, pl, vth, vtl, gbh, gbl);

        tsplit(Wo + WO, Dd, Dd);
        gemm_mma<EPI_RES><<<dim3(Dd / 128, BS / 128), 256, SMEM_MMA>>>(gbh, gbl, wh, wl, bo + i * Dd, x, tmp, nullptr, nullptr, BS, Dd, Dd);
        ln_kernel<<<BS, 128>>>(tmp, x, ln1g + i * Dd, ln1b + i * Dd, 0, gbh, gbl);

        tsplit(W1 + (size_t)i * Dd * FFf, Dd, FFf);
        gemm_mma<EPI_GELU><<<dim3(FFf / 128, BS / 128), 256, SMEM_MMA>>>(gbh, gbl, wh, wl, b1 + i * FFf, nullptr, nullptr, gah, gal, BS, FFf, Dd);

        tsplit(W2 + (size_t)i * FFf * Dd, FFf, Dd);
        gemm_mma<EPI_RES><<<dim3(Dd / 128, BS / 128), 256, SMEM_MMA>>>(gah, gal, wh, wl, b2 + i * Dd, x, tmp, nullptr, nullptr, BS, Dd, FFf);

        if (i == NL - 1) {
            ln_kernel<<<BS, 128>>>(tmp, out, ln2g + i * Dd, ln2b + i * Dd, 0, nullptr, nullptr);
        } else {
            ln_kernel<<<BS, 128>>>(tmp, x, ln2g + i * Dd, ln2b + i * Dd, 0, gbh, gbl);
        }
    }
}